// round 2
// baseline (speedup 1.0000x reference)
#include <cuda_runtime.h>
#include <cuda_bf16.h>
#include <mma.h>
#include <math.h>

using namespace nvcuda;

// ---------------- problem constants ----------------
static constexpr int BB    = 4;
static constexpr int HH    = 192;
static constexpr int WW    = 192;
static constexpr int DIM   = 256;
static constexpr int HEADS = 8;
static constexpr int HD    = 32;
static constexpr int WIN   = 8;
static constexpr int SHIFT = 4;
static constexpr int HID   = 1024;

static constexpr int L     = HH * WW;          // 36864
static constexpr int MROWS = BB * L;           // 147456
static constexpr int NWB   = HH / WIN;         // 24
static constexpr int NWIN  = BB * NWB * NWB;   // 2304
static constexpr float SCALE = 0.17677669529663687f; // 1/sqrt(32)

// ---------------- scratch (static device memory; no allocation) ----------------
__device__ float g_h   [(size_t)MROWS * DIM];        // LN1 out
__device__ float g_qkv [(size_t)MROWS * 3 * DIM];    // qkv
__device__ float g_attn[(size_t)MROWS * DIM];        // attention out (windowed row order)
__device__ float g_x2  [(size_t)MROWS * DIM];        // shortcut + proj
__device__ float g_ln2 [(size_t)MROWS * DIM];        // LN2 out
__device__ float g_hid [(size_t)MROWS * HID];        // MLP hidden

// windowed row -> original token index (shift roll map, shared by gather & scatter)
__device__ __forceinline__ int win_row_to_token(int r) {
    int widx = r >> 6;
    int t    = r & 63;
    int b    = widx / (NWB * NWB);
    int wrem = widx - b * (NWB * NWB);
    int wh   = wrem / NWB;
    int ww   = wrem - wh * NWB;
    int ty   = t >> 3, tx = t & 7;
    int hp   = wh * WIN + ty + SHIFT; if (hp >= HH) hp -= HH;
    int wp   = ww * WIN + tx + SHIFT; if (wp >= WW) wp -= WW;
    return b * L + hp * WW + wp;
}

// ---------------- LayerNorm (fp32 -> fp32), one warp per row ----------------
__global__ void ln_kernel(const float* __restrict__ x, const float* __restrict__ g,
                          const float* __restrict__ b, float* __restrict__ out) {
    int gw   = (blockIdx.x * blockDim.x + threadIdx.x) >> 5;   // row
    int lane = threadIdx.x & 31;
    const float4* rp = (const float4*)(x + (size_t)gw * DIM);
    float4 a0 = rp[lane * 2], a1 = rp[lane * 2 + 1];
    float s  = a0.x + a0.y + a0.z + a0.w + a1.x + a1.y + a1.z + a1.w;
    float sq = a0.x*a0.x + a0.y*a0.y + a0.z*a0.z + a0.w*a0.w
             + a1.x*a1.x + a1.y*a1.y + a1.z*a1.z + a1.w*a1.w;
    #pragma unroll
    for (int o = 16; o; o >>= 1) {
        s  += __shfl_xor_sync(0xffffffffu, s,  o);
        sq += __shfl_xor_sync(0xffffffffu, sq, o);
    }
    float mean = s * (1.0f / DIM);
    float var  = sq * (1.0f / DIM) - mean * mean;
    float rstd = rsqrtf(var + 1e-5f);
    const float4* gp = (const float4*)g;
    const float4* bp = (const float4*)b;
    float4 g0 = gp[lane*2], g1 = gp[lane*2+1], b0 = bp[lane*2], b1 = bp[lane*2+1];
    float4 o0, o1;
    o0.x = (a0.x - mean) * rstd * g0.x + b0.x;
    o0.y = (a0.y - mean) * rstd * g0.y + b0.y;
    o0.z = (a0.z - mean) * rstd * g0.z + b0.z;
    o0.w = (a0.w - mean) * rstd * g0.w + b0.w;
    o1.x = (a1.x - mean) * rstd * g1.x + b1.x;
    o1.y = (a1.y - mean) * rstd * g1.y + b1.y;
    o1.z = (a1.z - mean) * rstd * g1.z + b1.z;
    o1.w = (a1.w - mean) * rstd * g1.w + b1.w;
    float4* op = (float4*)(out + (size_t)gw * DIM);
    op[lane * 2]     = o0;
    op[lane * 2 + 1] = o1;
}

// ---------------- GEMM: C[M,N] = A[M,K] @ B[K,N], tf32 x tf32 -> fp32 ----------------
// 256 threads, tile 128x128x32, warp grid 4(M) x 2(N), warp tile 32x64.
static constexpr int GBM = 128, GBN = 128, GBK = 32;
static constexpr int LDA_S = GBK + 4;     // 36 (floats)
static constexpr int LDB_S = GBN + 4;     // 132
static constexpr int LDC_S = 132;
static constexpr int SMEM_GEMM = GBM * LDC_S * 4;   // 67584 B (covers load stage 35328 B)

static constexpr int EPI_QKV = 0, EPI_PROJ = 1, EPI_FC1 = 2, EPI_FC2 = 3;

template<class Frag>
__device__ __forceinline__ void to_tf32(Frag& f) {
    #pragma unroll
    for (int t = 0; t < f.num_elements; t++) f.x[t] = wmma::__float_to_tf32(f.x[t]);
}

template<int EPI>
__global__ void gemm_tf32(const float* __restrict__ A,
                          const float* __restrict__ Bm,
                          const float* __restrict__ bias,
                          const float* __restrict__ res,
                          float* __restrict__ outF,
                          int M, int N, int K) {
    extern __shared__ char smem[];
    float* As = (float*)smem;                  // [128][36]
    float* Bs = As + GBM * LDA_S;              // [32][132]
    float* Cs = (float*)smem;                  // [128][132] (aliased)

    int tid  = threadIdx.x;
    int warp = tid >> 5;
    int wm   = warp >> 1;          // 0..3
    int wn   = warp & 1;           // 0..1
    int bm   = blockIdx.y * GBM;
    int bn   = blockIdx.x * GBN;

    wmma::fragment<wmma::accumulator, 16, 16, 8, float> acc[2][4];
    #pragma unroll
    for (int i = 0; i < 2; i++)
        #pragma unroll
        for (int j = 0; j < 4; j++)
            wmma::fill_fragment(acc[i][j], 0.0f);

    for (int k0 = 0; k0 < K; k0 += GBK) {
        #pragma unroll
        for (int i = 0; i < 4; i++) {       // A: 1024 float4 chunks (128 rows x 8)
            int c = tid + i * 256;
            int r = c >> 3, cc = (c & 7) * 4;
            *(float4*)&As[r * LDA_S + cc] =
                *(const float4*)&A[(size_t)(bm + r) * K + k0 + cc];
        }
        #pragma unroll
        for (int i = 0; i < 4; i++) {       // B: 1024 float4 chunks (32 rows x 32)
            int c = tid + i * 256;
            int r = c >> 5, cc = (c & 31) * 4;
            *(float4*)&Bs[r * LDB_S + cc] =
                *(const float4*)&Bm[(size_t)(k0 + r) * N + bn + cc];
        }
        __syncthreads();
        #pragma unroll
        for (int kk = 0; kk < GBK; kk += 8) {
            wmma::fragment<wmma::matrix_a, 16, 16, 8, wmma::precision::tf32, wmma::row_major> af[2];
            wmma::fragment<wmma::matrix_b, 16, 16, 8, wmma::precision::tf32, wmma::row_major> bf[4];
            #pragma unroll
            for (int i = 0; i < 2; i++) {
                wmma::load_matrix_sync(af[i], &As[(wm * 32 + i * 16) * LDA_S + kk], LDA_S);
                to_tf32(af[i]);
            }
            #pragma unroll
            for (int j = 0; j < 4; j++) {
                wmma::load_matrix_sync(bf[j], &Bs[kk * LDB_S + wn * 64 + j * 16], LDB_S);
                to_tf32(bf[j]);
            }
            #pragma unroll
            for (int i = 0; i < 2; i++)
                #pragma unroll
                for (int j = 0; j < 4; j++)
                    wmma::mma_sync(acc[i][j], af[i], bf[j], acc[i][j]);
        }
        __syncthreads();
    }

    // stage C to smem, then coalesced elementwise epilogue
    #pragma unroll
    for (int i = 0; i < 2; i++)
        #pragma unroll
        for (int j = 0; j < 4; j++)
            wmma::store_matrix_sync(&Cs[(wm * 32 + i * 16) * LDC_S + wn * 64 + j * 16],
                                    acc[i][j], LDC_S, wmma::mem_row_major);
    __syncthreads();

    #pragma unroll 4
    for (int e = 0; e < 64; e++) {
        int idx = tid + e * 256;
        int r = idx >> 7, c = idx & 127;
        float v = Cs[r * LDC_S + c];
        int gr = bm + r, gc = bn + c;
        if (EPI == EPI_QKV) {
            outF[(size_t)gr * N + gc] = v + bias[gc];
        } else if (EPI == EPI_PROJ) {
            int tok = win_row_to_token(gr);
            size_t o = (size_t)tok * DIM + gc;
            outF[o] = v + bias[gc] + res[o];
        } else if (EPI == EPI_FC1) {
            float t = v + bias[gc];
            outF[(size_t)gr * N + gc] = 0.5f * t * (1.0f + erff(t * 0.70710678118654752f));
        } else { // EPI_FC2
            size_t o = (size_t)gr * N + gc;
            outF[o] = v + bias[gc] + res[o];
        }
    }
}

// ---------------- attention: one block per (window, head), 128 threads, tf32 ----------------
static constexpr int AQ_LD = 36;   // 32 + 4 pad (floats)
static constexpr int AS_LD = 68;   // 64 + 4 pad
// smem float offsets
static constexpr int OFF_Q = 0;
static constexpr int OFF_K = OFF_Q + 64 * AQ_LD;     // 2304
static constexpr int OFF_V = OFF_K + 64 * AQ_LD;     // 4608
static constexpr int OFF_S = OFF_V + 64 * AQ_LD;     // 6912
static constexpr int OFF_P = OFF_S + 64 * AS_LD;     // 11264
static constexpr int OFF_B = OFF_P + 64 * AS_LD;     // 15616
static constexpr int OFF_T = OFF_B + 228;            // 15844 (225 rounded to 228)
static constexpr int ATT_SMEM = (OFF_T + 64) * 4;    // 63632 B

__global__ void attn_kernel(const float* __restrict__ qkv,
                            const float* __restrict__ table,
                            float* __restrict__ outp) {
    extern __shared__ float sm[];
    float* sQ = sm + OFF_Q;
    float* sK = sm + OFF_K;
    float* sV = sm + OFF_V;
    float* sS = sm + OFF_S;
    float* sP = sm + OFF_P;
    float* sB = sm + OFF_B;
    int*   sTok = (int*)(sm + OFF_T);

    int widx = blockIdx.x, head = blockIdx.y;
    int tid = threadIdx.x, lane = tid & 31, w = tid >> 5;

    if (tid < 225) sB[tid] = table[tid * HEADS + head];
    if (tid < 64)  sTok[tid] = win_row_to_token(widx * 64 + tid);
    __syncthreads();

    // gather q,k,v rows: 64 x 32 floats each (8 float4 per row)
    #pragma unroll
    for (int i = 0; i < 4; i++) {
        int c = tid + i * 128;
        int r = c >> 3, cc = (c & 7) * 4;
        size_t base = (size_t)sTok[r] * (3 * DIM) + head * HD + cc;
        *(float4*)&sQ[r * AQ_LD + cc] = *(const float4*)&qkv[base];
        *(float4*)&sK[r * AQ_LD + cc] = *(const float4*)&qkv[base + DIM];
        *(float4*)&sV[r * AQ_LD + cc] = *(const float4*)&qkv[base + 2 * DIM];
    }
    __syncthreads();

    // S = Q @ K^T  (each warp: 16 rows x 64 cols)
    {
        wmma::fragment<wmma::accumulator, 16, 16, 8, float> acc[4];
        #pragma unroll
        for (int j = 0; j < 4; j++) wmma::fill_fragment(acc[j], 0.0f);
        #pragma unroll
        for (int kk = 0; kk < 32; kk += 8) {
            wmma::fragment<wmma::matrix_a, 16, 16, 8, wmma::precision::tf32, wmma::row_major> af;
            wmma::load_matrix_sync(af, &sQ[(w * 16) * AQ_LD + kk], AQ_LD);
            to_tf32(af);
            #pragma unroll
            for (int j = 0; j < 4; j++) {
                wmma::fragment<wmma::matrix_b, 16, 16, 8, wmma::precision::tf32, wmma::col_major> bf;
                wmma::load_matrix_sync(bf, &sK[(j * 16) * AQ_LD + kk], AQ_LD);
                to_tf32(bf);
                wmma::mma_sync(acc[j], af, bf, acc[j]);
            }
        }
        #pragma unroll
        for (int j = 0; j < 4; j++)
            wmma::store_matrix_sync(&sS[(w * 16) * AS_LD + j * 16], acc[j], AS_LD, wmma::mem_row_major);
    }
    __syncthreads();

    // softmax(S*scale + relbias) -> P
    #pragma unroll 2
    for (int rr = 0; rr < 16; rr++) {
        int r = w * 16 + rr;
        int yi = r >> 3, xi = r & 7;
        int c0 = lane, c1 = lane + 32;
        int i0 = (yi - (c0 >> 3) + 7) * 15 + (xi - (c0 & 7) + 7);
        int i1 = (yi - (c1 >> 3) + 7) * 15 + (xi - (c1 & 7) + 7);
        float v0 = sS[r * AS_LD + c0] * SCALE + sB[i0];
        float v1 = sS[r * AS_LD + c1] * SCALE + sB[i1];
        float m = fmaxf(v0, v1);
        #pragma unroll
        for (int o = 16; o; o >>= 1) m = fmaxf(m, __shfl_xor_sync(0xffffffffu, m, o));
        float e0 = __expf(v0 - m), e1 = __expf(v1 - m);
        float s = e0 + e1;
        #pragma unroll
        for (int o = 16; o; o >>= 1) s += __shfl_xor_sync(0xffffffffu, s, o);
        float inv = 1.0f / s;
        sP[r * AS_LD + c0] = e0 * inv;
        sP[r * AS_LD + c1] = e1 * inv;
    }
    __syncthreads();

    // O = P @ V  (each warp: 16 rows x 32 cols)
    {
        wmma::fragment<wmma::accumulator, 16, 16, 8, float> acc[2];
        #pragma unroll
        for (int j = 0; j < 2; j++) wmma::fill_fragment(acc[j], 0.0f);
        #pragma unroll
        for (int k0 = 0; k0 < 64; k0 += 8) {
            wmma::fragment<wmma::matrix_a, 16, 16, 8, wmma::precision::tf32, wmma::row_major> af;
            wmma::load_matrix_sync(af, &sP[(w * 16) * AS_LD + k0], AS_LD);
            to_tf32(af);
            #pragma unroll
            for (int j = 0; j < 2; j++) {
                wmma::fragment<wmma::matrix_b, 16, 16, 8, wmma::precision::tf32, wmma::row_major> bf;
                wmma::load_matrix_sync(bf, &sV[k0 * AQ_LD + j * 16], AQ_LD);
                to_tf32(bf);
                wmma::mma_sync(acc[j], af, bf, acc[j]);
            }
        }
        __syncthreads();   // all warps done with sS before overwrite
        #pragma unroll
        for (int j = 0; j < 2; j++)
            wmma::store_matrix_sync(&sS[(w * 16) * AS_LD + j * 16], acc[j], AS_LD, wmma::mem_row_major);
    }
    __syncthreads();

    // write O (windowed row order) for proj GEMM
    #pragma unroll
    for (int i = 0; i < 16; i++) {
        int idx = tid + i * 128;
        int r = idx >> 5, c = idx & 31;
        outp[((size_t)widx * 64 + r) * DIM + head * HD + c] = sS[r * AS_LD + c];
    }
}

// ---------------- launch ----------------
extern "C" void kernel_launch(void* const* d_in, const int* in_sizes, int n_in,
                              void* d_out, int out_size) {
    const float* x        = (const float*)d_in[0];
    const float* norm1_g  = (const float*)d_in[1];
    const float* norm1_b  = (const float*)d_in[2];
    const float* qkv_w    = (const float*)d_in[3];
    const float* qkv_b    = (const float*)d_in[4];
    const float* bias_tab = (const float*)d_in[5];
    const float* proj_w   = (const float*)d_in[6];
    const float* proj_b   = (const float*)d_in[7];
    const float* norm2_g  = (const float*)d_in[8];
    const float* norm2_b  = (const float*)d_in[9];
    const float* fc1_w    = (const float*)d_in[10];
    const float* fc1_b    = (const float*)d_in[11];
    const float* fc2_w    = (const float*)d_in[12];
    const float* fc2_b    = (const float*)d_in[13];
    float* out            = (float*)d_out;

    void *p;
    cudaGetSymbolAddress(&p, g_h);     float* ph    = (float*)p;
    cudaGetSymbolAddress(&p, g_qkv);   float* pqkv  = (float*)p;
    cudaGetSymbolAddress(&p, g_attn);  float* pattn = (float*)p;
    cudaGetSymbolAddress(&p, g_x2);    float* px2   = (float*)p;
    cudaGetSymbolAddress(&p, g_ln2);   float* pln2  = (float*)p;
    cudaGetSymbolAddress(&p, g_hid);   float* phid  = (float*)p;

    cudaFuncSetAttribute(gemm_tf32<EPI_QKV>,  cudaFuncAttributeMaxDynamicSharedMemorySize, SMEM_GEMM);
    cudaFuncSetAttribute(gemm_tf32<EPI_PROJ>, cudaFuncAttributeMaxDynamicSharedMemorySize, SMEM_GEMM);
    cudaFuncSetAttribute(gemm_tf32<EPI_FC1>,  cudaFuncAttributeMaxDynamicSharedMemorySize, SMEM_GEMM);
    cudaFuncSetAttribute(gemm_tf32<EPI_FC2>,  cudaFuncAttributeMaxDynamicSharedMemorySize, SMEM_GEMM);
    cudaFuncSetAttribute(attn_kernel,         cudaFuncAttributeMaxDynamicSharedMemorySize, ATT_SMEM);

    // 1. LN1
    ln_kernel<<<MROWS/8, 256>>>(x, norm1_g, norm1_b, ph);

    // 2. QKV GEMM
    gemm_tf32<EPI_QKV><<<dim3(3*DIM/GBN, MROWS/GBM), 256, SMEM_GEMM>>>(
        ph, qkv_w, qkv_b, nullptr, pqkv, MROWS, 3*DIM, DIM);

    // 3. windowed attention
    attn_kernel<<<dim3(NWIN, HEADS), 128, ATT_SMEM>>>(pqkv, bias_tab, pattn);

    // 4. proj GEMM + shortcut (scatter through inverse roll) -> x2
    gemm_tf32<EPI_PROJ><<<dim3(DIM/GBN, MROWS/GBM), 256, SMEM_GEMM>>>(
        pattn, proj_w, proj_b, x, px2, MROWS, DIM, DIM);

    // 5. LN2
    ln_kernel<<<MROWS/8, 256>>>(px2, norm2_g, norm2_b, pln2);

    // 6. fc1 + GELU
    gemm_tf32<EPI_FC1><<<dim3(HID/GBN, MROWS/GBM), 256, SMEM_GEMM>>>(
        pln2, fc1_w, fc1_b, nullptr, phid, MROWS, HID, DIM);

    // 7. fc2 + residual -> out
    gemm_tf32<EPI_FC2><<<dim3(DIM/GBN, MROWS/GBM), 256, SMEM_GEMM>>>(
        phid, fc2_w, fc2_b, px2, out, MROWS, DIM, HID);
}

// round 4
// speedup vs baseline: 1.4621x; 1.4621x over previous
#include <cuda_runtime.h>
#include <cuda_bf16.h>
#include <mma.h>
#include <math.h>
#include <cstdint>

using namespace nvcuda;

// ---------------- problem constants ----------------
static constexpr int BB    = 4;
static constexpr int HH    = 192;
static constexpr int WW    = 192;
static constexpr int DIM   = 256;
static constexpr int HEADS = 8;
static constexpr int HD    = 32;
static constexpr int WIN   = 8;
static constexpr int SHIFT = 4;
static constexpr int HID   = 1024;

static constexpr int L     = HH * WW;          // 36864
static constexpr int MROWS = BB * L;           // 147456
static constexpr int NWB   = HH / WIN;         // 24
static constexpr int NWIN  = BB * NWB * NWB;   // 2304
static constexpr float SCALE = 0.17677669529663687f; // 1/sqrt(32)

// ---------------- scratch (static device memory; no allocation) ----------------
// "3K split" layout: A3[M][3K] with columns [0,K)=hi, [K,2K)=lo, [2K,3K)=hi
//                    B3[3K][N] with rows    [0,K)=hi, [K,2K)=hi, [2K,3K)=lo
// so plain bf16 GEMM(A3,B3) = A_hi B_hi + A_lo B_hi + A_hi B_lo  (near-fp32)
__device__ __nv_bfloat16 g_h3   [(size_t)MROWS * 3 * DIM];   // LN1 out, split
__device__ float         g_qkv  [(size_t)MROWS * 3 * DIM];   // qkv fp32
__device__ __nv_bfloat16 g_attn3[(size_t)MROWS * 3 * DIM];   // attn out, split (windowed order)
__device__ float         g_x2   [(size_t)MROWS * DIM];       // shortcut + proj
__device__ __nv_bfloat16 g_ln23 [(size_t)MROWS * 3 * DIM];   // LN2 out, split
__device__ __nv_bfloat16 g_hid3 [(size_t)MROWS * 3 * HID];   // MLP hidden, split

__device__ __nv_bfloat16 g_wqkv3 [3 * DIM * 3 * DIM];
__device__ __nv_bfloat16 g_wproj3[3 * DIM * DIM];
__device__ __nv_bfloat16 g_wfc13 [3 * DIM * HID];
__device__ __nv_bfloat16 g_wfc23 [3 * HID * DIM];

__device__ __forceinline__ void split2(float v, __nv_bfloat16& hi, __nv_bfloat16& lo) {
    hi = __float2bfloat16(v);
    lo = __float2bfloat16(v - __bfloat162float(hi));
}

// windowed row -> original token index (shift roll map, shared by gather & scatter)
__device__ __forceinline__ int win_row_to_token(int r) {
    int widx = r >> 6;
    int t    = r & 63;
    int b    = widx / (NWB * NWB);
    int wrem = widx - b * (NWB * NWB);
    int wh   = wrem / NWB;
    int ww   = wrem - wh * NWB;
    int ty   = t >> 3, tx = t & 7;
    int hp   = wh * WIN + ty + SHIFT; if (hp >= HH) hp -= HH;
    int wp   = ww * WIN + tx + SHIFT; if (wp >= WW) wp -= WW;
    return b * L + hp * WW + wp;
}

// ---------------- weight fp32 [K][N] -> split bf16 [3K][N] ----------------
__global__ void cvt_split(const float* __restrict__ w, __nv_bfloat16* __restrict__ w3,
                          int K, int N) {
    int i = blockIdx.x * blockDim.x + threadIdx.x;
    if (i >= K * N) return;
    __nv_bfloat16 hi, lo;
    split2(w[i], hi, lo);
    w3[i]             = hi;   // rows [0,K)   = hi
    w3[K * N + i]     = hi;   // rows [K,2K)  = hi
    w3[2 * K * N + i] = lo;   // rows [2K,3K) = lo
}

// ---------------- LayerNorm fp32 -> split bf16 [M][768], one warp per row ----------------
__global__ void ln_split_kernel(const float* __restrict__ x, const float* __restrict__ g,
                                const float* __restrict__ b, __nv_bfloat16* __restrict__ out) {
    int gw   = (blockIdx.x * blockDim.x + threadIdx.x) >> 5;   // row
    int lane = threadIdx.x & 31;
    const float4* rp = (const float4*)(x + (size_t)gw * DIM);
    float4 a0 = rp[lane * 2], a1 = rp[lane * 2 + 1];
    float s  = a0.x + a0.y + a0.z + a0.w + a1.x + a1.y + a1.z + a1.w;
    float sq = a0.x*a0.x + a0.y*a0.y + a0.z*a0.z + a0.w*a0.w
             + a1.x*a1.x + a1.y*a1.y + a1.z*a1.z + a1.w*a1.w;
    #pragma unroll
    for (int o = 16; o; o >>= 1) {
        s  += __shfl_xor_sync(0xffffffffu, s,  o);
        sq += __shfl_xor_sync(0xffffffffu, sq, o);
    }
    float mean = s * (1.0f / DIM);
    float var  = sq * (1.0f / DIM) - mean * mean;
    float rstd = rsqrtf(var + 1e-5f);
    const float4* gp = (const float4*)g;
    const float4* bp = (const float4*)b;
    float4 g0 = gp[lane*2], g1 = gp[lane*2+1], b0 = bp[lane*2], b1 = bp[lane*2+1];
    float y[8];
    y[0] = (a0.x - mean) * rstd * g0.x + b0.x;
    y[1] = (a0.y - mean) * rstd * g0.y + b0.y;
    y[2] = (a0.z - mean) * rstd * g0.z + b0.z;
    y[3] = (a0.w - mean) * rstd * g0.w + b0.w;
    y[4] = (a1.x - mean) * rstd * g1.x + b1.x;
    y[5] = (a1.y - mean) * rstd * g1.y + b1.y;
    y[6] = (a1.z - mean) * rstd * g1.z + b1.z;
    y[7] = (a1.w - mean) * rstd * g1.w + b1.w;
    __nv_bfloat16 hi[8], lo[8];
    #pragma unroll
    for (int i = 0; i < 8; i++) split2(y[i], hi[i], lo[i]);
    __nv_bfloat16* base = out + (size_t)gw * (3 * DIM) + lane * 8;
    *(uint4*)(base)           = *(uint4*)hi;
    *(uint4*)(base + DIM)     = *(uint4*)lo;
    *(uint4*)(base + 2 * DIM) = *(uint4*)hi;
}

// ---------------- GEMM: C[M,N] = A3[M,K3] @ B3[K3,N], bf16 -> fp32, cp.async pipeline ----------------
static constexpr int Bb_M = 128, Bb_N = 128, Bb_K = 32, STAGES = 4;
static constexpr int LDA = Bb_K + 8;     // 40 bf16 (80B rows)
static constexpr int LDB = Bb_N + 8;     // 136 bf16 (272B rows)
static constexpr int A_ST = Bb_M * LDA;  // 5120 elems/stage
static constexpr int B_ST = Bb_K * LDB;  // 4352 elems/stage
static constexpr int LDC_S = 132;
static constexpr int SMEM_GEMM = STAGES * (A_ST + B_ST) * 2;   // 75776 B (Cs 67584 fits)

static constexpr int EPI_QKV = 0, EPI_PROJ = 1, EPI_FC1 = 2, EPI_FC2 = 3;

__device__ __forceinline__ void cpa16(void* sptr, const void* gptr) {
    unsigned int s = (unsigned int)__cvta_generic_to_shared(sptr);
    asm volatile("cp.async.cg.shared.global [%0], [%1], 16;\n" :: "r"(s), "l"(gptr));
}

template<int EPI>
__global__ void __launch_bounds__(256)
gemm_bf16s(const __nv_bfloat16* __restrict__ A,
           const __nv_bfloat16* __restrict__ Bm,
           const float* __restrict__ bias,
           const float* __restrict__ res,
           float* __restrict__ outF,
           __nv_bfloat16* __restrict__ out3,
           int M, int N, int K3) {
    extern __shared__ char smem[];
    __nv_bfloat16* smA = (__nv_bfloat16*)smem;
    __nv_bfloat16* smB = smA + STAGES * A_ST;
    float*         Cs  = (float*)smem;                 // aliased for epilogue

    int tid  = threadIdx.x;
    int warp = tid >> 5;
    int wm   = warp >> 1;          // 0..3
    int wn   = warp & 1;           // 0..1
    int bm   = blockIdx.y * Bb_M;
    int bn   = blockIdx.x * Bb_N;
    int T    = K3 / Bb_K;

    wmma::fragment<wmma::accumulator, 16, 16, 16, float> acc[2][4];
    #pragma unroll
    for (int i = 0; i < 2; i++)
        #pragma unroll
        for (int j = 0; j < 4; j++)
            wmma::fill_fragment(acc[i][j], 0.0f);

    auto issue_tile = [&](int t) {
        if (t < T) {
            int k0 = t * Bb_K;
            __nv_bfloat16* As = smA + (t & (STAGES - 1)) * A_ST;
            __nv_bfloat16* Bs = smB + (t & (STAGES - 1)) * B_ST;
            #pragma unroll
            for (int i = 0; i < 2; i++) {            // A: 512 x 16B
                int c = tid + i * 256;
                int r = c >> 2, cc = (c & 3) * 8;
                cpa16(&As[r * LDA + cc], &A[(size_t)(bm + r) * K3 + k0 + cc]);
            }
            #pragma unroll
            for (int i = 0; i < 2; i++) {            // B: 512 x 16B
                int c = tid + i * 256;
                int r = c >> 4, cc = (c & 15) * 8;
                cpa16(&Bs[r * LDB + cc], &Bm[(size_t)(k0 + r) * N + bn + cc]);
            }
        }
        asm volatile("cp.async.commit_group;\n" ::);
    };

    #pragma unroll
    for (int s = 0; s < STAGES - 1; s++) issue_tile(s);

    for (int t = 0; t < T; t++) {
        asm volatile("cp.async.wait_group 2;\n" ::);   // STAGES-2 outstanding
        __syncthreads();
        const __nv_bfloat16* As = smA + (t & (STAGES - 1)) * A_ST;
        const __nv_bfloat16* Bs = smB + (t & (STAGES - 1)) * B_ST;
        #pragma unroll
        for (int kk = 0; kk < Bb_K; kk += 16) {
            wmma::fragment<wmma::matrix_a, 16, 16, 16, __nv_bfloat16, wmma::row_major> af[2];
            wmma::fragment<wmma::matrix_b, 16, 16, 16, __nv_bfloat16, wmma::row_major> bf[4];
            #pragma unroll
            for (int i = 0; i < 2; i++)
                wmma::load_matrix_sync(af[i], &As[(wm * 32 + i * 16) * LDA + kk], LDA);
            #pragma unroll
            for (int j = 0; j < 4; j++)
                wmma::load_matrix_sync(bf[j], &Bs[kk * LDB + wn * 64 + j * 16], LDB);
            #pragma unroll
            for (int i = 0; i < 2; i++)
                #pragma unroll
                for (int j = 0; j < 4; j++)
                    wmma::mma_sync(acc[i][j], af[i], bf[j], acc[i][j]);
        }
        issue_tile(t + STAGES - 1);
    }

    asm volatile("cp.async.wait_all;\n" ::);
    __syncthreads();

    // stage C to smem, then coalesced elementwise epilogue
    #pragma unroll
    for (int i = 0; i < 2; i++)
        #pragma unroll
        for (int j = 0; j < 4; j++)
            wmma::store_matrix_sync(&Cs[(wm * 32 + i * 16) * LDC_S + wn * 64 + j * 16],
                                    acc[i][j], LDC_S, wmma::mem_row_major);
    __syncthreads();

    #pragma unroll 4
    for (int e = 0; e < 64; e++) {
        int idx = tid + e * 256;
        int r = idx >> 7, c = idx & 127;
        float v = Cs[r * LDC_S + c];
        int gr = bm + r, gc = bn + c;
        if (EPI == EPI_QKV) {
            outF[(size_t)gr * N + gc] = v + bias[gc];
        } else if (EPI == EPI_PROJ) {
            int tok = win_row_to_token(gr);
            size_t o = (size_t)tok * DIM + gc;
            outF[o] = v + bias[gc] + res[o];
        } else if (EPI == EPI_FC1) {
            float t = v + bias[gc];
            float gl = 0.5f * t * (1.0f + erff(t * 0.70710678118654752f));
            __nv_bfloat16 hi, lo;
            split2(gl, hi, lo);
            size_t base = (size_t)gr * (3 * HID) + gc;
            out3[base]            = hi;
            out3[base + HID]      = lo;
            out3[base + 2 * HID]  = hi;
        } else { // EPI_FC2
            size_t o = (size_t)gr * N + gc;
            outF[o] = v + bias[gc] + res[o];
        }
    }
}

// ---------------- attention: one block per (window, head), 128 threads, tf32 ----------------
static constexpr int AQ_LD = 36;
static constexpr int AS_LD = 68;
static constexpr int OFF_Q = 0;
static constexpr int OFF_K = OFF_Q + 64 * AQ_LD;
static constexpr int OFF_V = OFF_K + 64 * AQ_LD;
static constexpr int OFF_S = OFF_V + 64 * AQ_LD;
static constexpr int OFF_P = OFF_S + 64 * AS_LD;
static constexpr int OFF_B = OFF_P + 64 * AS_LD;
static constexpr int OFF_T = OFF_B + 228;
static constexpr int ATT_SMEM = (OFF_T + 64) * 4;

template<class Frag>
__device__ __forceinline__ void to_tf32(Frag& f) {
    #pragma unroll
    for (int t = 0; t < f.num_elements; t++) f.x[t] = wmma::__float_to_tf32(f.x[t]);
}

__global__ void attn_kernel(const float* __restrict__ qkv,
                            const float* __restrict__ table,
                            __nv_bfloat16* __restrict__ out3) {
    extern __shared__ float sm[];
    float* sQ = sm + OFF_Q;
    float* sK = sm + OFF_K;
    float* sV = sm + OFF_V;
    float* sS = sm + OFF_S;
    float* sP = sm + OFF_P;
    float* sB = sm + OFF_B;
    int*   sTok = (int*)(sm + OFF_T);

    int widx = blockIdx.x, head = blockIdx.y;
    int tid = threadIdx.x, lane = tid & 31, w = tid >> 5;

    if (tid < 225) sB[tid] = table[tid * HEADS + head];
    if (tid < 64)  sTok[tid] = win_row_to_token(widx * 64 + tid);
    __syncthreads();

    #pragma unroll
    for (int i = 0; i < 4; i++) {
        int c = tid + i * 128;
        int r = c >> 3, cc = (c & 7) * 4;
        size_t base = (size_t)sTok[r] * (3 * DIM) + head * HD + cc;
        *(float4*)&sQ[r * AQ_LD + cc] = *(const float4*)&qkv[base];
        *(float4*)&sK[r * AQ_LD + cc] = *(const float4*)&qkv[base + DIM];
        *(float4*)&sV[r * AQ_LD + cc] = *(const float4*)&qkv[base + 2 * DIM];
    }
    __syncthreads();

    // S = Q @ K^T
    {
        wmma::fragment<wmma::accumulator, 16, 16, 8, float> acc[4];
        #pragma unroll
        for (int j = 0; j < 4; j++) wmma::fill_fragment(acc[j], 0.0f);
        #pragma unroll
        for (int kk = 0; kk < 32; kk += 8) {
            wmma::fragment<wmma::matrix_a, 16, 16, 8, wmma::precision::tf32, wmma::row_major> af;
            wmma::load_matrix_sync(af, &sQ[(w * 16) * AQ_LD + kk], AQ_LD);
            to_tf32(af);
            #pragma unroll
            for (int j = 0; j < 4; j++) {
                wmma::fragment<wmma::matrix_b, 16, 16, 8, wmma::precision::tf32, wmma::col_major> bf;
                wmma::load_matrix_sync(bf, &sK[(j * 16) * AQ_LD + kk], AQ_LD);
                to_tf32(bf);
                wmma::mma_sync(acc[j], af, bf, acc[j]);
            }
        }
        #pragma unroll
        for (int j = 0; j < 4; j++)
            wmma::store_matrix_sync(&sS[(w * 16) * AS_LD + j * 16], acc[j], AS_LD, wmma::mem_row_major);
    }
    __syncthreads();

    // softmax(S*scale + relbias) -> P
    #pragma unroll 2
    for (int rr = 0; rr < 16; rr++) {
        int r = w * 16 + rr;
        int yi = r >> 3, xi = r & 7;
        int c0 = lane, c1 = lane + 32;
        int i0 = (yi - (c0 >> 3) + 7) * 15 + (xi - (c0 & 7) + 7);
        int i1 = (yi - (c1 >> 3) + 7) * 15 + (xi - (c1 & 7) + 7);
        float v0 = sS[r * AS_LD + c0] * SCALE + sB[i0];
        float v1 = sS[r * AS_LD + c1] * SCALE + sB[i1];
        float m = fmaxf(v0, v1);
        #pragma unroll
        for (int o = 16; o; o >>= 1) m = fmaxf(m, __shfl_xor_sync(0xffffffffu, m, o));
        float e0 = __expf(v0 - m), e1 = __expf(v1 - m);
        float s = e0 + e1;
        #pragma unroll
        for (int o = 16; o; o >>= 1) s += __shfl_xor_sync(0xffffffffu, s, o);
        float inv = 1.0f / s;
        sP[r * AS_LD + c0] = e0 * inv;
        sP[r * AS_LD + c1] = e1 * inv;
    }
    __syncthreads();

    // O = P @ V
    {
        wmma::fragment<wmma::accumulator, 16, 16, 8, float> acc[2];
        #pragma unroll
        for (int j = 0; j < 2; j++) wmma::fill_fragment(acc[j], 0.0f);
        #pragma unroll
        for (int k0 = 0; k0 < 64; k0 += 8) {
            wmma::fragment<wmma::matrix_a, 16, 16, 8, wmma::precision::tf32, wmma::row_major> af;
            wmma::load_matrix_sync(af, &sP[(w * 16) * AS_LD + k0], AS_LD);
            to_tf32(af);
            #pragma unroll
            for (int j = 0; j < 2; j++) {
                wmma::fragment<wmma::matrix_b, 16, 16, 8, wmma::precision::tf32, wmma::row_major> bf;
                wmma::load_matrix_sync(bf, &sV[k0 * AQ_LD + j * 16], AQ_LD);
                to_tf32(bf);
                wmma::mma_sync(acc[j], af, bf, acc[j]);
            }
        }
        __syncthreads();
        #pragma unroll
        for (int j = 0; j < 2; j++)
            wmma::store_matrix_sync(&sS[(w * 16) * AS_LD + j * 16], acc[j], AS_LD, wmma::mem_row_major);
    }
    __syncthreads();

    // write O (windowed row order) as hi|lo|hi split for proj GEMM
    #pragma unroll
    for (int i = 0; i < 16; i++) {
        int idx = tid + i * 128;
        int r = idx >> 5, c = idx & 31;
        float v = sS[r * AS_LD + c];
        __nv_bfloat16 hi, lo;
        split2(v, hi, lo);
        size_t base = ((size_t)widx * 64 + r) * (3 * DIM) + head * HD + c;
        out3[base]           = hi;
        out3[base + DIM]     = lo;
        out3[base + 2 * DIM] = hi;
    }
}

// ---------------- launch ----------------
extern "C" void kernel_launch(void* const* d_in, const int* in_sizes, int n_in,
                              void* d_out, int out_size) {
    const float* x        = (const float*)d_in[0];
    const float* norm1_g  = (const float*)d_in[1];
    const float* norm1_b  = (const float*)d_in[2];
    const float* qkv_w    = (const float*)d_in[3];
    const float* qkv_b    = (const float*)d_in[4];
    const float* bias_tab = (const float*)d_in[5];
    const float* proj_w   = (const float*)d_in[6];
    const float* proj_b   = (const float*)d_in[7];
    const float* norm2_g  = (const float*)d_in[8];
    const float* norm2_b  = (const float*)d_in[9];
    const float* fc1_w    = (const float*)d_in[10];
    const float* fc1_b    = (const float*)d_in[11];
    const float* fc2_w    = (const float*)d_in[12];
    const float* fc2_b    = (const float*)d_in[13];
    float* out            = (float*)d_out;

    void *p;
    cudaGetSymbolAddress(&p, g_h3);    __nv_bfloat16* ph3   = (__nv_bfloat16*)p;
    cudaGetSymbolAddress(&p, g_qkv);   float*         pqkv  = (float*)p;
    cudaGetSymbolAddress(&p, g_attn3); __nv_bfloat16* pat3  = (__nv_bfloat16*)p;
    cudaGetSymbolAddress(&p, g_x2);    float*         px2   = (float*)p;
    cudaGetSymbolAddress(&p, g_ln23);  __nv_bfloat16* pln23 = (__nv_bfloat16*)p;
    cudaGetSymbolAddress(&p, g_hid3);  __nv_bfloat16* phid3 = (__nv_bfloat16*)p;
    cudaGetSymbolAddress(&p, g_wqkv3); __nv_bfloat16* pwq3  = (__nv_bfloat16*)p;
    cudaGetSymbolAddress(&p, g_wproj3);__nv_bfloat16* pwp3  = (__nv_bfloat16*)p;
    cudaGetSymbolAddress(&p, g_wfc13); __nv_bfloat16* pw13  = (__nv_bfloat16*)p;
    cudaGetSymbolAddress(&p, g_wfc23); __nv_bfloat16* pw23  = (__nv_bfloat16*)p;

    cudaFuncSetAttribute(gemm_bf16s<EPI_QKV>,  cudaFuncAttributeMaxDynamicSharedMemorySize, SMEM_GEMM);
    cudaFuncSetAttribute(gemm_bf16s<EPI_PROJ>, cudaFuncAttributeMaxDynamicSharedMemorySize, SMEM_GEMM);
    cudaFuncSetAttribute(gemm_bf16s<EPI_FC1>,  cudaFuncAttributeMaxDynamicSharedMemorySize, SMEM_GEMM);
    cudaFuncSetAttribute(gemm_bf16s<EPI_FC2>,  cudaFuncAttributeMaxDynamicSharedMemorySize, SMEM_GEMM);
    cudaFuncSetAttribute(attn_kernel,          cudaFuncAttributeMaxDynamicSharedMemorySize, ATT_SMEM);

    // 0. split weights (tiny)
    cvt_split<<<(DIM*3*DIM + 255)/256, 256>>>(qkv_w,  pwq3, DIM, 3*DIM);
    cvt_split<<<(DIM*DIM   + 255)/256, 256>>>(proj_w, pwp3, DIM, DIM);
    cvt_split<<<(DIM*HID   + 255)/256, 256>>>(fc1_w,  pw13, DIM, HID);
    cvt_split<<<(HID*DIM   + 255)/256, 256>>>(fc2_w,  pw23, HID, DIM);

    // 1. LN1 -> h3 (split)
    ln_split_kernel<<<MROWS/8, 256>>>(x, norm1_g, norm1_b, ph3);

    // 2. QKV GEMM (K3=768) -> qkv fp32
    gemm_bf16s<EPI_QKV><<<dim3(3*DIM/Bb_N, MROWS/Bb_M), 256, SMEM_GEMM>>>(
        ph3, pwq3, qkv_b, nullptr, pqkv, nullptr, MROWS, 3*DIM, 3*DIM);

    // 3. windowed attention (tf32) -> attn3 (split, windowed order)
    attn_kernel<<<dim3(NWIN, HEADS), 128, ATT_SMEM>>>(pqkv, bias_tab, pat3);

    // 4. proj GEMM (K3=768) + shortcut scatter -> x2 fp32
    gemm_bf16s<EPI_PROJ><<<dim3(DIM/Bb_N, MROWS/Bb_M), 256, SMEM_GEMM>>>(
        pat3, pwp3, proj_b, x, px2, nullptr, MROWS, DIM, 3*DIM);

    // 5. LN2 -> ln2_3 (split)
    ln_split_kernel<<<MROWS/8, 256>>>(px2, norm2_g, norm2_b, pln23);

    // 6. fc1 GEMM (K3=768) + GELU -> hid3 (split)
    gemm_bf16s<EPI_FC1><<<dim3(HID/Bb_N, MROWS/Bb_M), 256, SMEM_GEMM>>>(
        pln23, pw13, fc1_b, nullptr, nullptr, phid3, MROWS, HID, 3*DIM);

    // 7. fc2 GEMM (K3=3072) + residual -> out
    gemm_bf16s<EPI_FC2><<<dim3(DIM/Bb_N, MROWS/Bb_M), 256, SMEM_GEMM>>>(
        phid3, pw23, fc2_b, px2, out, nullptr, MROWS, DIM, 3*HID);
}

// round 6
// speedup vs baseline: 1.8443x; 1.2614x over previous
#include <cuda_runtime.h>
#include <cuda_bf16.h>
#include <mma.h>
#include <math.h>
#include <cstdint>

using namespace nvcuda;

// ---------------- problem constants ----------------
static constexpr int BB    = 4;
static constexpr int HH    = 192;
static constexpr int WW    = 192;
static constexpr int DIM   = 256;
static constexpr int HEADS = 8;
static constexpr int HD    = 32;
static constexpr int WIN   = 8;
static constexpr int SHIFT = 4;
static constexpr int HID   = 1024;

static constexpr int L     = HH * WW;          // 36864
static constexpr int MROWS = BB * L;           // 147456
static constexpr int NWB   = HH / WIN;         // 24
static constexpr int NWIN  = BB * NWB * NWB;   // 2304
static constexpr float SCALE = 0.17677669529663687f; // 1/sqrt(32)

// ---------------- scratch ----------------
// 2-component storage: A2[M][2K] = [hi | lo], W2[2K][N] = [hi ; lo].
// In-kernel products: Ahi*Bhi + Alo*Bhi (+ Ahi*Blo for 3-term GEMMs) ~ fp32.
__device__ __nv_bfloat16 g_h2   [(size_t)MROWS * 2 * DIM];   // LN1 out
__device__ float         g_qkv  [(size_t)MROWS * 3 * DIM];   // qkv fp32
__device__ __nv_bfloat16 g_attn2[(size_t)MROWS * 2 * DIM];   // attn out (windowed order)
__device__ float         g_x2   [(size_t)MROWS * DIM];
__device__ __nv_bfloat16 g_ln22 [(size_t)MROWS * 2 * DIM];
__device__ __nv_bfloat16 g_hid2 [(size_t)MROWS * 2 * HID];

__device__ __nv_bfloat16 g_wqkv2 [2 * DIM * 3 * DIM];   // [512][768]
__device__ __nv_bfloat16 g_wproj2[2 * DIM * DIM];       // [512][256]
__device__ __nv_bfloat16 g_wfc12 [2 * DIM * HID];       // [512][1024]
__device__ __nv_bfloat16 g_wfc22 [2 * HID * DIM];       // [2048][256]

__device__ __forceinline__ void split2(float v, __nv_bfloat16& hi, __nv_bfloat16& lo) {
    hi = __float2bfloat16(v);
    lo = __float2bfloat16(v - __bfloat162float(hi));
}

// windowed row -> original token index (shift roll map, gather & scatter)
__device__ __forceinline__ int win_row_to_token(int r) {
    int widx = r >> 6;
    int t    = r & 63;
    int b    = widx / (NWB * NWB);
    int wrem = widx - b * (NWB * NWB);
    int wh   = wrem / NWB;
    int ww   = wrem - wh * NWB;
    int ty   = t >> 3, tx = t & 7;
    int hp   = wh * WIN + ty + SHIFT; if (hp >= HH) hp -= HH;
    int wp   = ww * WIN + tx + SHIFT; if (wp >= WW) wp -= WW;
    return b * L + hp * WW + wp;
}

// ---------------- weight fp32 [K][N] -> split bf16 [2K][N] ----------------
__global__ void cvt_split2(const float* __restrict__ w, __nv_bfloat16* __restrict__ w2,
                           int K, int N) {
    int i = blockIdx.x * blockDim.x + threadIdx.x;
    if (i >= K * N) return;
    __nv_bfloat16 hi, lo;
    split2(w[i], hi, lo);
    w2[i]         = hi;    // rows [0,K)  = hi
    w2[K * N + i] = lo;    // rows [K,2K) = lo
}

// ---------------- LayerNorm fp32 -> split bf16 [M][2K], one warp per row ----------------
__global__ void ln_split_kernel(const float* __restrict__ x, const float* __restrict__ g,
                                const float* __restrict__ b, __nv_bfloat16* __restrict__ out) {
    int gw   = (blockIdx.x * blockDim.x + threadIdx.x) >> 5;
    int lane = threadIdx.x & 31;
    const float4* rp = (const float4*)(x + (size_t)gw * DIM);
    float4 a0 = rp[lane * 2], a1 = rp[lane * 2 + 1];
    float s  = a0.x + a0.y + a0.z + a0.w + a1.x + a1.y + a1.z + a1.w;
    float sq = a0.x*a0.x + a0.y*a0.y + a0.z*a0.z + a0.w*a0.w
             + a1.x*a1.x + a1.y*a1.y + a1.z*a1.z + a1.w*a1.w;
    #pragma unroll
    for (int o = 16; o; o >>= 1) {
        s  += __shfl_xor_sync(0xffffffffu, s,  o);
        sq += __shfl_xor_sync(0xffffffffu, sq, o);
    }
    float mean = s * (1.0f / DIM);
    float var  = sq * (1.0f / DIM) - mean * mean;
    float rstd = rsqrtf(var + 1e-5f);
    const float4* gp = (const float4*)g;
    const float4* bp = (const float4*)b;
    float4 g0 = gp[lane*2], g1 = gp[lane*2+1], b0 = bp[lane*2], b1 = bp[lane*2+1];
    float y[8];
    y[0] = (a0.x - mean) * rstd * g0.x + b0.x;
    y[1] = (a0.y - mean) * rstd * g0.y + b0.y;
    y[2] = (a0.z - mean) * rstd * g0.z + b0.z;
    y[3] = (a0.w - mean) * rstd * g0.w + b0.w;
    y[4] = (a1.x - mean) * rstd * g1.x + b1.x;
    y[5] = (a1.y - mean) * rstd * g1.y + b1.y;
    y[6] = (a1.z - mean) * rstd * g1.z + b1.z;
    y[7] = (a1.w - mean) * rstd * g1.w + b1.w;
    __nv_bfloat16 hi[8], lo[8];
    #pragma unroll
    for (int i = 0; i < 8; i++) split2(y[i], hi[i], lo[i]);
    __nv_bfloat16* base = out + (size_t)gw * (2 * DIM) + lane * 8;
    *(uint4*)(base)       = *(uint4*)hi;
    *(uint4*)(base + DIM) = *(uint4*)lo;
}

// ---------------- GEMM: C[M,N] = sum of split products, bf16 wmma, double-buffered ----------------
static constexpr int Bb_M = 128, Bb_N = 128, Bb_K = 32;
static constexpr int LDA = Bb_K + 8;     // 40
static constexpr int LDB = Bb_N + 8;     // 136
static constexpr int AH_ST = Bb_M * LDA; // 5120
static constexpr int BH_ST = Bb_K * LDB; // 4352
static constexpr int STAGE_E = 2 * AH_ST + 2 * BH_ST;   // 18944 elems
static constexpr int LDC_S = 132;
static constexpr int SMEM_GEMM = 2 * STAGE_E * 2;       // 75776 B (Cs 67584 fits)

static constexpr int EPI_QKV = 0, EPI_PROJ = 1, EPI_FC1 = 2, EPI_FC2 = 3;

__device__ __forceinline__ void cpa16(void* sptr, const void* gptr) {
    unsigned int s = (unsigned int)__cvta_generic_to_shared(sptr);
    asm volatile("cp.async.cg.shared.global [%0], [%1], 16;\n" :: "r"(s), "l"(gptr));
}

// TERMS = 3: Ahi*Bhi + Alo*Bhi + Ahi*Blo ; TERMS = 2: Ahi*Bhi + Alo*Bhi (B-lo never loaded)
template<int EPI, int TERMS>
__global__ void __launch_bounds__(256, 2)
gemm2(const __nv_bfloat16* __restrict__ A,      // [M][2K]
      const __nv_bfloat16* __restrict__ Bm,     // [2K][N]
      const float* __restrict__ bias,
      const float* __restrict__ res,
      float* __restrict__ outF,
      __nv_bfloat16* __restrict__ out2,
      int N, int K) {
    extern __shared__ char smem[];
    __nv_bfloat16* sm = (__nv_bfloat16*)smem;
    float*         Cs = (float*)smem;              // aliased epilogue staging

    int tid  = threadIdx.x;
    int warp = tid >> 5;
    int wm   = warp >> 1;          // 0..3
    int wn   = warp & 1;           // 0..1
    int bm   = blockIdx.x * Bb_M;
    int bn   = blockIdx.y * Bb_N;
    int K2   = 2 * K;
    int T    = K / Bb_K;

    wmma::fragment<wmma::accumulator, 16, 16, 16, float> acc[2][4];
    #pragma unroll
    for (int i = 0; i < 2; i++)
        #pragma unroll
        for (int j = 0; j < 4; j++)
            wmma::fill_fragment(acc[i][j], 0.0f);

    auto loads = [&](int t) {
        int k0 = t * Bb_K;
        __nv_bfloat16* AH = sm + (t & 1) * STAGE_E;
        __nv_bfloat16* AL = AH + AH_ST;
        __nv_bfloat16* BH = AL + AH_ST;
        __nv_bfloat16* BL = BH + BH_ST;
        #pragma unroll
        for (int i = 0; i < 2; i++) {            // A: 512 chunks x 16B per comp
            int c = tid + i * 256;
            int r = c >> 2, cc = (c & 3) * 8;
            const __nv_bfloat16* src = A + (size_t)(bm + r) * K2 + k0 + cc;
            cpa16(&AH[r * LDA + cc], src);
            cpa16(&AL[r * LDA + cc], src + K);
        }
        #pragma unroll
        for (int i = 0; i < 2; i++) {            // B: 512 chunks x 16B per comp
            int c = tid + i * 256;
            int r = c >> 4, cc = (c & 15) * 8;
            cpa16(&BH[r * LDB + cc], Bm + (size_t)(k0 + r) * N + bn + cc);
            if (TERMS == 3)
                cpa16(&BL[r * LDB + cc], Bm + (size_t)(K + k0 + r) * N + bn + cc);
        }
        asm volatile("cp.async.commit_group;\n" ::);
    };

    loads(0);

    for (int t = 0; t < T; t++) {
        if (t + 1 < T) loads(t + 1);
        else           asm volatile("cp.async.commit_group;\n" ::);
        asm volatile("cp.async.wait_group 1;\n" ::);   // stage t resident
        __syncthreads();

        const __nv_bfloat16* AH = sm + (t & 1) * STAGE_E;
        const __nv_bfloat16* AL = AH + AH_ST;
        const __nv_bfloat16* BH = AL + AH_ST;
        const __nv_bfloat16* BL = BH + BH_ST;

        #pragma unroll
        for (int kk = 0; kk < Bb_K; kk += 16) {
            wmma::fragment<wmma::matrix_a, 16, 16, 16, __nv_bfloat16, wmma::row_major> ah[2], al[2];
            wmma::fragment<wmma::matrix_b, 16, 16, 16, __nv_bfloat16, wmma::row_major> bf[4];
            #pragma unroll
            for (int i = 0; i < 2; i++) {
                wmma::load_matrix_sync(ah[i], &AH[(wm * 32 + i * 16) * LDA + kk], LDA);
                wmma::load_matrix_sync(al[i], &AL[(wm * 32 + i * 16) * LDA + kk], LDA);
            }
            #pragma unroll
            for (int j = 0; j < 4; j++)
                wmma::load_matrix_sync(bf[j], &BH[kk * LDB + wn * 64 + j * 16], LDB);
            #pragma unroll
            for (int i = 0; i < 2; i++)
                #pragma unroll
                for (int j = 0; j < 4; j++) {
                    wmma::mma_sync(acc[i][j], ah[i], bf[j], acc[i][j]);
                    wmma::mma_sync(acc[i][j], al[i], bf[j], acc[i][j]);
                }
            if (TERMS == 3) {
                #pragma unroll
                for (int j = 0; j < 4; j++)
                    wmma::load_matrix_sync(bf[j], &BL[kk * LDB + wn * 64 + j * 16], LDB);
                #pragma unroll
                for (int i = 0; i < 2; i++)
                    #pragma unroll
                    for (int j = 0; j < 4; j++)
                        wmma::mma_sync(acc[i][j], ah[i], bf[j], acc[i][j]);
            }
        }
        __syncthreads();   // done reading stage t before t+2 overwrites (next iter's loads)
    }

    asm volatile("cp.async.wait_all;\n" ::);
    __syncthreads();

    // stage C to smem, coalesced elementwise epilogue
    #pragma unroll
    for (int i = 0; i < 2; i++)
        #pragma unroll
        for (int j = 0; j < 4; j++)
            wmma::store_matrix_sync(&Cs[(wm * 32 + i * 16) * LDC_S + wn * 64 + j * 16],
                                    acc[i][j], LDC_S, wmma::mem_row_major);
    __syncthreads();

    #pragma unroll 4
    for (int e = 0; e < 64; e++) {
        int idx = tid + e * 256;
        int r = idx >> 7, c = idx & 127;
        float v = Cs[r * LDC_S + c];
        int gr = bm + r, gc = bn + c;
        if (EPI == EPI_QKV) {
            outF[(size_t)gr * N + gc] = v + bias[gc];
        } else if (EPI == EPI_PROJ) {
            int tok = win_row_to_token(gr);
            size_t o = (size_t)tok * DIM + gc;
            outF[o] = v + bias[gc] + res[o];
        } else if (EPI == EPI_FC1) {
            float t = v + bias[gc];
            float gl = 0.5f * t * (1.0f + erff(t * 0.70710678118654752f));
            __nv_bfloat16 hi, lo;
            split2(gl, hi, lo);
            size_t base = (size_t)gr * (2 * HID) + gc;
            out2[base]       = hi;
            out2[base + HID] = lo;
        } else { // EPI_FC2
            size_t o = (size_t)gr * N + gc;
            outF[o] = v + bias[gc] + res[o];
        }
    }
}

// ---------------- attention: one block per (window, head), 128 threads, tf32 ----------------
static constexpr int AQ_LD = 36;
static constexpr int AS_LD = 68;
static constexpr int OFF_Q = 0;
static constexpr int OFF_K = OFF_Q + 64 * AQ_LD;
static constexpr int OFF_V = OFF_K + 64 * AQ_LD;
static constexpr int OFF_S = OFF_V + 64 * AQ_LD;
static constexpr int OFF_P = OFF_S + 64 * AS_LD;
static constexpr int OFF_B = OFF_P + 64 * AS_LD;
static constexpr int OFF_T = OFF_B + 228;
static constexpr int ATT_SMEM = (OFF_T + 64) * 4;

template<class Frag>
__device__ __forceinline__ void to_tf32(Frag& f) {
    #pragma unroll
    for (int t = 0; t < f.num_elements; t++) f.x[t] = wmma::__float_to_tf32(f.x[t]);
}

__global__ void attn_kernel(const float* __restrict__ qkv,
                            const float* __restrict__ table,
                            __nv_bfloat16* __restrict__ out2) {
    extern __shared__ float sm[];
    float* sQ = sm + OFF_Q;
    float* sK = sm + OFF_K;
    float* sV = sm + OFF_V;
    float* sS = sm + OFF_S;
    float* sP = sm + OFF_P;
    float* sB = sm + OFF_B;
    int*   sTok = (int*)(sm + OFF_T);

    int widx = blockIdx.x, head = blockIdx.y;
    int tid = threadIdx.x, lane = tid & 31, w = tid >> 5;

    if (tid < 225) sB[tid] = table[tid * HEADS + head];
    if (tid < 64)  sTok[tid] = win_row_to_token(widx * 64 + tid);
    __syncthreads();

    #pragma unroll
    for (int i = 0; i < 4; i++) {
        int c = tid + i * 128;
        int r = c >> 3, cc = (c & 7) * 4;
        size_t base = (size_t)sTok[r] * (3 * DIM) + head * HD + cc;
        *(float4*)&sQ[r * AQ_LD + cc] = *(const float4*)&qkv[base];
        *(float4*)&sK[r * AQ_LD + cc] = *(const float4*)&qkv[base + DIM];
        *(float4*)&sV[r * AQ_LD + cc] = *(const float4*)&qkv[base + 2 * DIM];
    }
    __syncthreads();

    {
        wmma::fragment<wmma::accumulator, 16, 16, 8, float> acc[4];
        #pragma unroll
        for (int j = 0; j < 4; j++) wmma::fill_fragment(acc[j], 0.0f);
        #pragma unroll
        for (int kk = 0; kk < 32; kk += 8) {
            wmma::fragment<wmma::matrix_a, 16, 16, 8, wmma::precision::tf32, wmma::row_major> af;
            wmma::load_matrix_sync(af, &sQ[(w * 16) * AQ_LD + kk], AQ_LD);
            to_tf32(af);
            #pragma unroll
            for (int j = 0; j < 4; j++) {
                wmma::fragment<wmma::matrix_b, 16, 16, 8, wmma::precision::tf32, wmma::col_major> bf;
                wmma::load_matrix_sync(bf, &sK[(j * 16) * AQ_LD + kk], AQ_LD);
                to_tf32(bf);
                wmma::mma_sync(acc[j], af, bf, acc[j]);
            }
        }
        #pragma unroll
        for (int j = 0; j < 4; j++)
            wmma::store_matrix_sync(&sS[(w * 16) * AS_LD + j * 16], acc[j], AS_LD, wmma::mem_row_major);
    }
    __syncthreads();

    #pragma unroll 2
    for (int rr = 0; rr < 16; rr++) {
        int r = w * 16 + rr;
        int yi = r >> 3, xi = r & 7;
        int c0 = lane, c1 = lane + 32;
        int i0 = (yi - (c0 >> 3) + 7) * 15 + (xi - (c0 & 7) + 7);
        int i1 = (yi - (c1 >> 3) + 7) * 15 + (xi - (c1 & 7) + 7);
        float v0 = sS[r * AS_LD + c0] * SCALE + sB[i0];
        float v1 = sS[r * AS_LD + c1] * SCALE + sB[i1];
        float m = fmaxf(v0, v1);
        #pragma unroll
        for (int o = 16; o; o >>= 1) m = fmaxf(m, __shfl_xor_sync(0xffffffffu, m, o));
        float e0 = __expf(v0 - m), e1 = __expf(v1 - m);
        float s = e0 + e1;
        #pragma unroll
        for (int o = 16; o; o >>= 1) s += __shfl_xor_sync(0xffffffffu, s, o);
        float inv = 1.0f / s;
        sP[r * AS_LD + c0] = e0 * inv;
        sP[r * AS_LD + c1] = e1 * inv;
    }
    __syncthreads();

    {
        wmma::fragment<wmma::accumulator, 16, 16, 8, float> acc[2];
        #pragma unroll
        for (int j = 0; j < 2; j++) wmma::fill_fragment(acc[j], 0.0f);
        #pragma unroll
        for (int k0 = 0; k0 < 64; k0 += 8) {
            wmma::fragment<wmma::matrix_a, 16, 16, 8, wmma::precision::tf32, wmma::row_major> af;
            wmma::load_matrix_sync(af, &sP[(w * 16) * AS_LD + k0], AS_LD);
            to_tf32(af);
            #pragma unroll
            for (int j = 0; j < 2; j++) {
                wmma::fragment<wmma::matrix_b, 16, 16, 8, wmma::precision::tf32, wmma::row_major> bf;
                wmma::load_matrix_sync(bf, &sV[k0 * AQ_LD + j * 16], AQ_LD);
                to_tf32(bf);
                wmma::mma_sync(acc[j], af, bf, acc[j]);
            }
        }
        __syncthreads();
        #pragma unroll
        for (int j = 0; j < 2; j++)
            wmma::store_matrix_sync(&sS[(w * 16) * AS_LD + j * 16], acc[j], AS_LD, wmma::mem_row_major);
    }
    __syncthreads();

    // write O (windowed row order) as hi|lo split for proj GEMM
    #pragma unroll
    for (int i = 0; i < 16; i++) {
        int idx = tid + i * 128;
        int r = idx >> 5, c = idx & 31;
        float v = sS[r * AS_LD + c];
        __nv_bfloat16 hi, lo;
        split2(v, hi, lo);
        size_t base = ((size_t)widx * 64 + r) * (2 * DIM) + head * HD + c;
        out2[base]       = hi;
        out2[base + DIM] = lo;
    }
}

// ---------------- launch ----------------
extern "C" void kernel_launch(void* const* d_in, const int* in_sizes, int n_in,
                              void* d_out, int out_size) {
    const float* x        = (const float*)d_in[0];
    const float* norm1_g  = (const float*)d_in[1];
    const float* norm1_b  = (const float*)d_in[2];
    const float* qkv_w    = (const float*)d_in[3];
    const float* qkv_b    = (const float*)d_in[4];
    const float* bias_tab = (const float*)d_in[5];
    const float* proj_w   = (const float*)d_in[6];
    const float* proj_b   = (const float*)d_in[7];
    const float* norm2_g  = (const float*)d_in[8];
    const float* norm2_b  = (const float*)d_in[9];
    const float* fc1_w    = (const float*)d_in[10];
    const float* fc1_b    = (const float*)d_in[11];
    const float* fc2_w    = (const float*)d_in[12];
    const float* fc2_b    = (const float*)d_in[13];
    float* out            = (float*)d_out;

    void *p;
    cudaGetSymbolAddress(&p, g_h2);    __nv_bfloat16* ph2   = (__nv_bfloat16*)p;
    cudaGetSymbolAddress(&p, g_qkv);   float*         pqkv  = (float*)p;
    cudaGetSymbolAddress(&p, g_attn2); __nv_bfloat16* pat2  = (__nv_bfloat16*)p;
    cudaGetSymbolAddress(&p, g_x2);    float*         px2   = (float*)p;
    cudaGetSymbolAddress(&p, g_ln22);  __nv_bfloat16* pln22 = (__nv_bfloat16*)p;
    cudaGetSymbolAddress(&p, g_hid2);  __nv_bfloat16* phid2 = (__nv_bfloat16*)p;
    cudaGetSymbolAddress(&p, g_wqkv2); __nv_bfloat16* pwq2  = (__nv_bfloat16*)p;
    cudaGetSymbolAddress(&p, g_wproj2);__nv_bfloat16* pwp2  = (__nv_bfloat16*)p;
    cudaGetSymbolAddress(&p, g_wfc12); __nv_bfloat16* pw12  = (__nv_bfloat16*)p;
    cudaGetSymbolAddress(&p, g_wfc22); __nv_bfloat16* pw22  = (__nv_bfloat16*)p;

    cudaFuncSetAttribute((const void*)gemm2<EPI_QKV, 3>,  cudaFuncAttributeMaxDynamicSharedMemorySize, SMEM_GEMM);
    cudaFuncSetAttribute((const void*)gemm2<EPI_PROJ, 2>, cudaFuncAttributeMaxDynamicSharedMemorySize, SMEM_GEMM);
    cudaFuncSetAttribute((const void*)gemm2<EPI_FC1, 3>,  cudaFuncAttributeMaxDynamicSharedMemorySize, SMEM_GEMM);
    cudaFuncSetAttribute((const void*)gemm2<EPI_FC2, 2>,  cudaFuncAttributeMaxDynamicSharedMemorySize, SMEM_GEMM);
    cudaFuncSetAttribute(attn_kernel, cudaFuncAttributeMaxDynamicSharedMemorySize, ATT_SMEM);

    const int MT = MROWS / Bb_M;   // 1152

    // 0. split weights
    cvt_split2<<<(DIM*3*DIM + 255)/256, 256>>>(qkv_w,  pwq2, DIM, 3*DIM);
    cvt_split2<<<(DIM*DIM   + 255)/256, 256>>>(proj_w, pwp2, DIM, DIM);
    cvt_split2<<<(DIM*HID   + 255)/256, 256>>>(fc1_w,  pw12, DIM, HID);
    cvt_split2<<<(HID*DIM   + 255)/256, 256>>>(fc2_w,  pw22, HID, DIM);

    // 1. LN1 -> h2
    ln_split_kernel<<<MROWS/8, 256>>>(x, norm1_g, norm1_b, ph2);

    // 2. QKV GEMM (K=256, N=768, 3-term)
    gemm2<EPI_QKV, 3><<<dim3(MT, 3*DIM/Bb_N), 256, SMEM_GEMM>>>(
        ph2, pwq2, qkv_b, nullptr, pqkv, nullptr, 3*DIM, DIM);

    // 3. windowed attention (tf32) -> attn2 (windowed order)
    attn_kernel<<<dim3(NWIN, HEADS), 128, ATT_SMEM>>>(pqkv, bias_tab, pat2);

    // 4. proj GEMM (K=256, N=256, 2-term) + shortcut scatter -> x2
    gemm2<EPI_PROJ, 2><<<dim3(MT, DIM/Bb_N), 256, SMEM_GEMM>>>(
        pat2, pwp2, proj_b, x, px2, nullptr, DIM, DIM);

    // 5. LN2 -> ln22
    ln_split_kernel<<<MROWS/8, 256>>>(px2, norm2_g, norm2_b, pln22);

    // 6. fc1 GEMM (K=256, N=1024, 3-term) + GELU -> hid2
    gemm2<EPI_FC1, 3><<<dim3(MT, HID/Bb_N), 256, SMEM_GEMM>>>(
        pln22, pw12, fc1_b, nullptr, nullptr, phid2, HID, DIM);

    // 7. fc2 GEMM (K=1024, N=256, 2-term) + residual -> out
    gemm2<EPI_FC2, 2><<<dim3(MT, DIM/Bb_N), 256, SMEM_GEMM>>>(
        phid2, pw22, fc2_b, px2, out, nullptr, DIM, HID);
}

// round 7
// speedup vs baseline: 1.8760x; 1.0172x over previous
#include <cuda_runtime.h>
#include <cuda_bf16.h>
#include <mma.h>
#include <math.h>
#include <cstdint>

using namespace nvcuda;

// ---------------- problem constants ----------------
static constexpr int BB    = 4;
static constexpr int HH    = 192;
static constexpr int WW    = 192;
static constexpr int DIM   = 256;
static constexpr int HEADS = 8;
static constexpr int HD    = 32;
static constexpr int WIN   = 8;
static constexpr int SHIFT = 4;
static constexpr int HID   = 1024;

static constexpr int L     = HH * WW;          // 36864
static constexpr int MROWS = BB * L;           // 147456
static constexpr int NWB   = HH / WIN;         // 24
static constexpr int NWIN  = BB * NWB * NWB;   // 2304
static constexpr float SCALE = 0.17677669529663687f; // 1/sqrt(32)

// ---------------- scratch ----------------
// 2-component storage: A2[M][2K] = [hi | lo], W2[2K][N] = [hi ; lo].
__device__ __nv_bfloat16 g_h2   [(size_t)MROWS * 2 * DIM];
__device__ float         g_qkv  [(size_t)MROWS * 3 * DIM];
__device__ __nv_bfloat16 g_attn2[(size_t)MROWS * 2 * DIM];
__device__ float         g_x2   [(size_t)MROWS * DIM];
__device__ __nv_bfloat16 g_ln22 [(size_t)MROWS * 2 * DIM];
__device__ __nv_bfloat16 g_hid2 [(size_t)MROWS * 2 * HID];

__device__ __nv_bfloat16 g_wqkv2 [2 * DIM * 3 * DIM];
__device__ __nv_bfloat16 g_wproj2[2 * DIM * DIM];
__device__ __nv_bfloat16 g_wfc12 [2 * DIM * HID];
__device__ __nv_bfloat16 g_wfc22 [2 * HID * DIM];

__device__ __forceinline__ void split2(float v, __nv_bfloat16& hi, __nv_bfloat16& lo) {
    hi = __float2bfloat16(v);
    lo = __float2bfloat16(v - __bfloat162float(hi));
}

__device__ __forceinline__ int win_row_to_token(int r) {
    int widx = r >> 6;
    int t    = r & 63;
    int b    = widx / (NWB * NWB);
    int wrem = widx - b * (NWB * NWB);
    int wh   = wrem / NWB;
    int ww   = wrem - wh * NWB;
    int ty   = t >> 3, tx = t & 7;
    int hp   = wh * WIN + ty + SHIFT; if (hp >= HH) hp -= HH;
    int wp   = ww * WIN + tx + SHIFT; if (wp >= WW) wp -= WW;
    return b * L + hp * WW + wp;
}

// ---------------- weight fp32 [K][N] -> split bf16 [2K][N] ----------------
__global__ void cvt_split2(const float* __restrict__ w, __nv_bfloat16* __restrict__ w2,
                           int K, int N) {
    int i = blockIdx.x * blockDim.x + threadIdx.x;
    if (i >= K * N) return;
    __nv_bfloat16 hi, lo;
    split2(w[i], hi, lo);
    w2[i]         = hi;
    w2[K * N + i] = lo;
}

// ---------------- LayerNorm fp32 -> split bf16 [M][2K], one warp per row ----------------
__global__ void ln_split_kernel(const float* __restrict__ x, const float* __restrict__ g,
                                const float* __restrict__ b, __nv_bfloat16* __restrict__ out) {
    int gw   = (blockIdx.x * blockDim.x + threadIdx.x) >> 5;
    int lane = threadIdx.x & 31;
    const float4* rp = (const float4*)(x + (size_t)gw * DIM);
    float4 a0 = rp[lane * 2], a1 = rp[lane * 2 + 1];
    float s  = a0.x + a0.y + a0.z + a0.w + a1.x + a1.y + a1.z + a1.w;
    float sq = a0.x*a0.x + a0.y*a0.y + a0.z*a0.z + a0.w*a0.w
             + a1.x*a1.x + a1.y*a1.y + a1.z*a1.z + a1.w*a1.w;
    #pragma unroll
    for (int o = 16; o; o >>= 1) {
        s  += __shfl_xor_sync(0xffffffffu, s,  o);
        sq += __shfl_xor_sync(0xffffffffu, sq, o);
    }
    float mean = s * (1.0f / DIM);
    float var  = sq * (1.0f / DIM) - mean * mean;
    float rstd = rsqrtf(var + 1e-5f);
    const float4* gp = (const float4*)g;
    const float4* bp = (const float4*)b;
    float4 g0 = gp[lane*2], g1 = gp[lane*2+1], b0 = bp[lane*2], b1 = bp[lane*2+1];
    float y[8];
    y[0] = (a0.x - mean) * rstd * g0.x + b0.x;
    y[1] = (a0.y - mean) * rstd * g0.y + b0.y;
    y[2] = (a0.z - mean) * rstd * g0.z + b0.z;
    y[3] = (a0.w - mean) * rstd * g0.w + b0.w;
    y[4] = (a1.x - mean) * rstd * g1.x + b1.x;
    y[5] = (a1.y - mean) * rstd * g1.y + b1.y;
    y[6] = (a1.z - mean) * rstd * g1.z + b1.z;
    y[7] = (a1.w - mean) * rstd * g1.w + b1.w;
    __nv_bfloat16 hi[8], lo[8];
    #pragma unroll
    for (int i = 0; i < 8; i++) split2(y[i], hi[i], lo[i]);
    __nv_bfloat16* base = out + (size_t)gw * (2 * DIM) + lane * 8;
    *(uint4*)(base)       = *(uint4*)hi;
    *(uint4*)(base + DIM) = *(uint4*)lo;
}

// ---------------- GEMM: split products, bf16 wmma, 3-stage cp.async pipeline ----------------
static constexpr int Bb_M = 128, Bb_N = 128, Bb_K = 32, STAGES = 3;
static constexpr int LDA = Bb_K + 8;     // 40
static constexpr int LDB = Bb_N + 8;     // 136
static constexpr int AH_ST = Bb_M * LDA; // 5120
static constexpr int BH_ST = Bb_K * LDB; // 4352
static constexpr int STAGE_E = 2 * AH_ST + 2 * BH_ST;   // 18944 elems (37888 B)
static constexpr int LDC_S = 132;
static constexpr int SMEM_GEMM = STAGES * STAGE_E * 2;  // 113664 B (Cs 67584 aliases fine)

static constexpr int EPI_QKV = 0, EPI_PROJ = 1, EPI_FC1 = 2, EPI_FC2 = 3;

__device__ __forceinline__ void cpa16(void* sptr, const void* gptr) {
    unsigned int s = (unsigned int)__cvta_generic_to_shared(sptr);
    asm volatile("cp.async.cg.shared.global [%0], [%1], 16;\n" :: "r"(s), "l"(gptr));
}

// TERMS = 3: Ahi*Bhi + Alo*Bhi + Ahi*Blo ; TERMS = 2: Ahi*Bhi + Alo*Bhi
template<int EPI, int TERMS>
__global__ void __launch_bounds__(256, 2)
gemm2(const __nv_bfloat16* __restrict__ A,      // [M][2K]
      const __nv_bfloat16* __restrict__ Bm,     // [2K][N]
      const float* __restrict__ bias,
      const float* __restrict__ res,
      float* __restrict__ outF,
      __nv_bfloat16* __restrict__ out2,
      int N, int K) {
    extern __shared__ char smem[];
    __nv_bfloat16* sm = (__nv_bfloat16*)smem;
    float*         Cs = (float*)smem;

    int tid  = threadIdx.x;
    int warp = tid >> 5;
    int wm   = warp >> 1;          // 0..3
    int wn   = warp & 1;           // 0..1
    // N-tile in blockIdx.x (fastest): CTAs sharing bm co-reside -> A served from L2.
    int bn   = blockIdx.x * Bb_N;
    int bm   = blockIdx.y * Bb_M;
    int K2   = 2 * K;
    int T    = K / Bb_K;

    wmma::fragment<wmma::accumulator, 16, 16, 16, float> acc[2][4];
    #pragma unroll
    for (int i = 0; i < 2; i++)
        #pragma unroll
        for (int j = 0; j < 4; j++)
            wmma::fill_fragment(acc[i][j], 0.0f);

    auto loads = [&](int t) {
        int k0 = t * Bb_K;
        int st = t % STAGES;
        __nv_bfloat16* AH = sm + st * STAGE_E;
        __nv_bfloat16* AL = AH + AH_ST;
        __nv_bfloat16* BH = AL + AH_ST;
        __nv_bfloat16* BL = BH + BH_ST;
        #pragma unroll
        for (int i = 0; i < 2; i++) {
            int c = tid + i * 256;
            int r = c >> 2, cc = (c & 3) * 8;
            const __nv_bfloat16* src = A + (size_t)(bm + r) * K2 + k0 + cc;
            cpa16(&AH[r * LDA + cc], src);
            cpa16(&AL[r * LDA + cc], src + K);
        }
        #pragma unroll
        for (int i = 0; i < 2; i++) {
            int c = tid + i * 256;
            int r = c >> 4, cc = (c & 15) * 8;
            cpa16(&BH[r * LDB + cc], Bm + (size_t)(k0 + r) * N + bn + cc);
            if (TERMS == 3)
                cpa16(&BL[r * LDB + cc], Bm + (size_t)(K + k0 + r) * N + bn + cc);
        }
        asm volatile("cp.async.commit_group;\n" ::);
    };

    loads(0);
    loads(1);

    for (int t = 0; t < T; t++) {
        asm volatile("cp.async.wait_group 1;\n" ::);   // stage t resident
        __syncthreads();                               // also: all warps done reading stage t-1
        if (t + 2 < T) loads(t + 2);                   // overwrites stage (t-1)%3 — safe

        int st = t % STAGES;
        const __nv_bfloat16* AH = sm + st * STAGE_E;
        const __nv_bfloat16* AL = AH + AH_ST;
        const __nv_bfloat16* BH = AL + AH_ST;
        const __nv_bfloat16* BL = BH + BH_ST;

        #pragma unroll
        for (int kk = 0; kk < Bb_K; kk += 16) {
            wmma::fragment<wmma::matrix_a, 16, 16, 16, __nv_bfloat16, wmma::row_major> ah[2], al[2];
            wmma::fragment<wmma::matrix_b, 16, 16, 16, __nv_bfloat16, wmma::row_major> bf[4];
            #pragma unroll
            for (int i = 0; i < 2; i++) {
                wmma::load_matrix_sync(ah[i], &AH[(wm * 32 + i * 16) * LDA + kk], LDA);
                wmma::load_matrix_sync(al[i], &AL[(wm * 32 + i * 16) * LDA + kk], LDA);
            }
            #pragma unroll
            for (int j = 0; j < 4; j++)
                wmma::load_matrix_sync(bf[j], &BH[kk * LDB + wn * 64 + j * 16], LDB);
            #pragma unroll
            for (int i = 0; i < 2; i++)
                #pragma unroll
                for (int j = 0; j < 4; j++) {
                    wmma::mma_sync(acc[i][j], ah[i], bf[j], acc[i][j]);
                    wmma::mma_sync(acc[i][j], al[i], bf[j], acc[i][j]);
                }
            if (TERMS == 3) {
                #pragma unroll
                for (int j = 0; j < 4; j++)
                    wmma::load_matrix_sync(bf[j], &BL[kk * LDB + wn * 64 + j * 16], LDB);
                #pragma unroll
                for (int i = 0; i < 2; i++)
                    #pragma unroll
                    for (int j = 0; j < 4; j++)
                        wmma::mma_sync(acc[i][j], ah[i], bf[j], acc[i][j]);
            }
        }
    }

    asm volatile("cp.async.wait_all;\n" ::);
    __syncthreads();

    #pragma unroll
    for (int i = 0; i < 2; i++)
        #pragma unroll
        for (int j = 0; j < 4; j++)
            wmma::store_matrix_sync(&Cs[(wm * 32 + i * 16) * LDC_S + wn * 64 + j * 16],
                                    acc[i][j], LDC_S, wmma::mem_row_major);
    __syncthreads();

    #pragma unroll 4
    for (int e = 0; e < 64; e++) {
        int idx = tid + e * 256;
        int r = idx >> 7, c = idx & 127;
        float v = Cs[r * LDC_S + c];
        int gr = bm + r, gc = bn + c;
        if (EPI == EPI_QKV) {
            outF[(size_t)gr * N + gc] = v + bias[gc];
        } else if (EPI == EPI_PROJ) {
            int tok = win_row_to_token(gr);
            size_t o = (size_t)tok * DIM + gc;
            outF[o] = v + bias[gc] + res[o];
        } else if (EPI == EPI_FC1) {
            float t = v + bias[gc];
            float gl = 0.5f * t * (1.0f + erff(t * 0.70710678118654752f));
            __nv_bfloat16 hi, lo;
            split2(gl, hi, lo);
            size_t base = (size_t)gr * (2 * HID) + gc;
            out2[base]       = hi;
            out2[base + HID] = lo;
        } else { // EPI_FC2
            size_t o = (size_t)gr * N + gc;
            outF[o] = v + bias[gc] + res[o];
        }
    }
}

// ---------------- attention: one block per (window, head), 128 threads, tf32 ----------------
static constexpr int AQ_LD = 36;
static constexpr int AS_LD = 68;
static constexpr int OFF_Q = 0;
static constexpr int OFF_K = OFF_Q + 64 * AQ_LD;
static constexpr int OFF_V = OFF_K + 64 * AQ_LD;
static constexpr int OFF_S = OFF_V + 64 * AQ_LD;
static constexpr int OFF_P = OFF_S + 64 * AS_LD;
static constexpr int OFF_B = OFF_P + 64 * AS_LD;
static constexpr int OFF_T = OFF_B + 228;
static constexpr int ATT_SMEM = (OFF_T + 64) * 4;

template<class Frag>
__device__ __forceinline__ void to_tf32(Frag& f) {
    #pragma unroll
    for (int t = 0; t < f.num_elements; t++) f.x[t] = wmma::__float_to_tf32(f.x[t]);
}

__global__ void attn_kernel(const float* __restrict__ qkv,
                            const float* __restrict__ table,
                            __nv_bfloat16* __restrict__ out2) {
    extern __shared__ float sm[];
    float* sQ = sm + OFF_Q;
    float* sK = sm + OFF_K;
    float* sV = sm + OFF_V;
    float* sS = sm + OFF_S;
    float* sP = sm + OFF_P;
    float* sB = sm + OFF_B;
    int*   sTok = (int*)(sm + OFF_T);

    int widx = blockIdx.x, head = blockIdx.y;
    int tid = threadIdx.x, lane = tid & 31, w = tid >> 5;

    if (tid < 225) sB[tid] = table[tid * HEADS + head];
    if (tid < 64)  sTok[tid] = win_row_to_token(widx * 64 + tid);
    __syncthreads();

    #pragma unroll
    for (int i = 0; i < 4; i++) {
        int c = tid + i * 128;
        int r = c >> 3, cc = (c & 7) * 4;
        size_t base = (size_t)sTok[r] * (3 * DIM) + head * HD + cc;
        *(float4*)&sQ[r * AQ_LD + cc] = *(const float4*)&qkv[base];
        *(float4*)&sK[r * AQ_LD + cc] = *(const float4*)&qkv[base + DIM];
        *(float4*)&sV[r * AQ_LD + cc] = *(const float4*)&qkv[base + 2 * DIM];
    }
    __syncthreads();

    {
        wmma::fragment<wmma::accumulator, 16, 16, 8, float> acc[4];
        #pragma unroll
        for (int j = 0; j < 4; j++) wmma::fill_fragment(acc[j], 0.0f);
        #pragma unroll
        for (int kk = 0; kk < 32; kk += 8) {
            wmma::fragment<wmma::matrix_a, 16, 16, 8, wmma::precision::tf32, wmma::row_major> af;
            wmma::load_matrix_sync(af, &sQ[(w * 16) * AQ_LD + kk], AQ_LD);
            to_tf32(af);
            #pragma unroll
            for (int j = 0; j < 4; j++) {
                wmma::fragment<wmma::matrix_b, 16, 16, 8, wmma::precision::tf32, wmma::col_major> bf;
                wmma::load_matrix_sync(bf, &sK[(j * 16) * AQ_LD + kk], AQ_LD);
                to_tf32(bf);
                wmma::mma_sync(acc[j], af, bf, acc[j]);
            }
        }
        #pragma unroll
        for (int j = 0; j < 4; j++)
            wmma::store_matrix_sync(&sS[(w * 16) * AS_LD + j * 16], acc[j], AS_LD, wmma::mem_row_major);
    }
    __syncthreads();

    #pragma unroll 2
    for (int rr = 0; rr < 16; rr++) {
        int r = w * 16 + rr;
        int yi = r >> 3, xi = r & 7;
        int c0 = lane, c1 = lane + 32;
        int i0 = (yi - (c0 >> 3) + 7) * 15 + (xi - (c0 & 7) + 7);
        int i1 = (yi - (c1 >> 3) + 7) * 15 + (xi - (c1 & 7) + 7);
        float v0 = sS[r * AS_LD + c0] * SCALE + sB[i0];
        float v1 = sS[r * AS_LD + c1] * SCALE + sB[i1];
        float m = fmaxf(v0, v1);
        #pragma unroll
        for (int o = 16; o; o >>= 1) m = fmaxf(m, __shfl_xor_sync(0xffffffffu, m, o));
        float e0 = __expf(v0 - m), e1 = __expf(v1 - m);
        float s = e0 + e1;
        #pragma unroll
        for (int o = 16; o; o >>= 1) s += __shfl_xor_sync(0xffffffffu, s, o);
        float inv = 1.0f / s;
        sP[r * AS_LD + c0] = e0 * inv;
        sP[r * AS_LD + c1] = e1 * inv;
    }
    __syncthreads();

    {
        wmma::fragment<wmma::accumulator, 16, 16, 8, float> acc[2];
        #pragma unroll
        for (int j = 0; j < 2; j++) wmma::fill_fragment(acc[j], 0.0f);
        #pragma unroll
        for (int k0 = 0; k0 < 64; k0 += 8) {
            wmma::fragment<wmma::matrix_a, 16, 16, 8, wmma::precision::tf32, wmma::row_major> af;
            wmma::load_matrix_sync(af, &sP[(w * 16) * AS_LD + k0], AS_LD);
            to_tf32(af);
            #pragma unroll
            for (int j = 0; j < 2; j++) {
                wmma::fragment<wmma::matrix_b, 16, 16, 8, wmma::precision::tf32, wmma::row_major> bf;
                wmma::load_matrix_sync(bf, &sV[k0 * AQ_LD + j * 16], AQ_LD);
                to_tf32(bf);
                wmma::mma_sync(acc[j], af, bf, acc[j]);
            }
        }
        __syncthreads();
        #pragma unroll
        for (int j = 0; j < 2; j++)
            wmma::store_matrix_sync(&sS[(w * 16) * AS_LD + j * 16], acc[j], AS_LD, wmma::mem_row_major);
    }
    __syncthreads();

    #pragma unroll
    for (int i = 0; i < 16; i++) {
        int idx = tid + i * 128;
        int r = idx >> 5, c = idx & 31;
        float v = sS[r * AS_LD + c];
        __nv_bfloat16 hi, lo;
        split2(v, hi, lo);
        size_t base = ((size_t)widx * 64 + r) * (2 * DIM) + head * HD + c;
        out2[base]       = hi;
        out2[base + DIM] = lo;
    }
}

// ---------------- launch ----------------
extern "C" void kernel_launch(void* const* d_in, const int* in_sizes, int n_in,
                              void* d_out, int out_size) {
    const float* x        = (const float*)d_in[0];
    const float* norm1_g  = (const float*)d_in[1];
    const float* norm1_b  = (const float*)d_in[2];
    const float* qkv_w    = (const float*)d_in[3];
    const float* qkv_b    = (const float*)d_in[4];
    const float* bias_tab = (const float*)d_in[5];
    const float* proj_w   = (const float*)d_in[6];
    const float* proj_b   = (const float*)d_in[7];
    const float* norm2_g  = (const float*)d_in[8];
    const float* norm2_b  = (const float*)d_in[9];
    const float* fc1_w    = (const float*)d_in[10];
    const float* fc1_b    = (const float*)d_in[11];
    const float* fc2_w    = (const float*)d_in[12];
    const float* fc2_b    = (const float*)d_in[13];
    float* out            = (float*)d_out;

    void *p;
    cudaGetSymbolAddress(&p, g_h2);    __nv_bfloat16* ph2   = (__nv_bfloat16*)p;
    cudaGetSymbolAddress(&p, g_qkv);   float*         pqkv  = (float*)p;
    cudaGetSymbolAddress(&p, g_attn2); __nv_bfloat16* pat2  = (__nv_bfloat16*)p;
    cudaGetSymbolAddress(&p, g_x2);    float*         px2   = (float*)p;
    cudaGetSymbolAddress(&p, g_ln22);  __nv_bfloat16* pln22 = (__nv_bfloat16*)p;
    cudaGetSymbolAddress(&p, g_hid2);  __nv_bfloat16* phid2 = (__nv_bfloat16*)p;
    cudaGetSymbolAddress(&p, g_wqkv2); __nv_bfloat16* pwq2  = (__nv_bfloat16*)p;
    cudaGetSymbolAddress(&p, g_wproj2);__nv_bfloat16* pwp2  = (__nv_bfloat16*)p;
    cudaGetSymbolAddress(&p, g_wfc12); __nv_bfloat16* pw12  = (__nv_bfloat16*)p;
    cudaGetSymbolAddress(&p, g_wfc22); __nv_bfloat16* pw22  = (__nv_bfloat16*)p;

    cudaFuncSetAttribute((const void*)gemm2<EPI_QKV, 3>,  cudaFuncAttributeMaxDynamicSharedMemorySize, SMEM_GEMM);
    cudaFuncSetAttribute((const void*)gemm2<EPI_PROJ, 2>, cudaFuncAttributeMaxDynamicSharedMemorySize, SMEM_GEMM);
    cudaFuncSetAttribute((const void*)gemm2<EPI_FC1, 3>,  cudaFuncAttributeMaxDynamicSharedMemorySize, SMEM_GEMM);
    cudaFuncSetAttribute((const void*)gemm2<EPI_FC2, 2>,  cudaFuncAttributeMaxDynamicSharedMemorySize, SMEM_GEMM);
    cudaFuncSetAttribute(attn_kernel, cudaFuncAttributeMaxDynamicSharedMemorySize, ATT_SMEM);

    const int MT = MROWS / Bb_M;   // 1152

    // 0. split weights
    cvt_split2<<<(DIM*3*DIM + 255)/256, 256>>>(qkv_w,  pwq2, DIM, 3*DIM);
    cvt_split2<<<(DIM*DIM   + 255)/256, 256>>>(proj_w, pwp2, DIM, DIM);
    cvt_split2<<<(DIM*HID   + 255)/256, 256>>>(fc1_w,  pw12, DIM, HID);
    cvt_split2<<<(HID*DIM   + 255)/256, 256>>>(fc2_w,  pw22, HID, DIM);

    // 1. LN1 -> h2
    ln_split_kernel<<<MROWS/8, 256>>>(x, norm1_g, norm1_b, ph2);

    // 2. QKV GEMM (K=256, N=768, 3-term)   grid = (Ntiles, Mtiles)
    gemm2<EPI_QKV, 3><<<dim3(3*DIM/Bb_N, MT), 256, SMEM_GEMM>>>(
        ph2, pwq2, qkv_b, nullptr, pqkv, nullptr, 3*DIM, DIM);

    // 3. windowed attention (tf32) -> attn2 (windowed order)
    attn_kernel<<<dim3(NWIN, HEADS), 128, ATT_SMEM>>>(pqkv, bias_tab, pat2);

    // 4. proj GEMM (K=256, N=256, 2-term) + shortcut scatter -> x2
    gemm2<EPI_PROJ, 2><<<dim3(DIM/Bb_N, MT), 256, SMEM_GEMM>>>(
        pat2, pwp2, proj_b, x, px2, nullptr, DIM, DIM);

    // 5. LN2 -> ln22
    ln_split_kernel<<<MROWS/8, 256>>>(px2, norm2_g, norm2_b, pln22);

    // 6. fc1 GEMM (K=256, N=1024, 3-term) + GELU -> hid2
    gemm2<EPI_FC1, 3><<<dim3(HID/Bb_N, MT), 256, SMEM_GEMM>>>(
        pln22, pw12, fc1_b, nullptr, nullptr, phid2, HID, DIM);

    // 7. fc2 GEMM (K=1024, N=256, 2-term) + residual -> out
    gemm2<EPI_FC2, 2><<<dim3(DIM/Bb_N, MT), 256, SMEM_GEMM>>>(
        phid2, pw22, fc2_b, px2, out, nullptr, DIM, HID);
}

// round 8
// speedup vs baseline: 2.0124x; 1.0727x over previous
#include <cuda_runtime.h>
#include <cuda_bf16.h>
#include <mma.h>
#include <math.h>
#include <cstdint>

using namespace nvcuda;

// ---------------- problem constants ----------------
static constexpr int BB    = 4;
static constexpr int HH    = 192;
static constexpr int WW    = 192;
static constexpr int DIM   = 256;
static constexpr int HEADS = 8;
static constexpr int HD    = 32;
static constexpr int WIN   = 8;
static constexpr int SHIFT = 4;
static constexpr int HID   = 1024;

static constexpr int L     = HH * WW;          // 36864
static constexpr int MROWS = BB * L;           // 147456
static constexpr int NWB   = HH / WIN;         // 24
static constexpr int NWIN  = BB * NWB * NWB;   // 2304
static constexpr float SCALE = 0.17677669529663687f; // 1/sqrt(32)

// ---------------- scratch ----------------
// 2-component storage: A2[M][2K] = [hi | lo], W2[2K][N] = [hi ; lo].
__device__ __nv_bfloat16 g_h2   [(size_t)MROWS * 2 * DIM];
__device__ float         g_qkv  [(size_t)MROWS * 3 * DIM];
__device__ __nv_bfloat16 g_attn2[(size_t)MROWS * 2 * DIM];
__device__ float         g_x2   [(size_t)MROWS * DIM];
__device__ __nv_bfloat16 g_ln22 [(size_t)MROWS * 2 * DIM];
__device__ __nv_bfloat16 g_hid2 [(size_t)MROWS * 2 * HID];

__device__ __nv_bfloat16 g_wqkv2 [2 * DIM * 3 * DIM];
__device__ __nv_bfloat16 g_wproj2[2 * DIM * DIM];
__device__ __nv_bfloat16 g_wfc12 [2 * DIM * HID];
__device__ __nv_bfloat16 g_wfc22 [2 * HID * DIM];

__device__ __forceinline__ void split2(float v, __nv_bfloat16& hi, __nv_bfloat16& lo) {
    hi = __float2bfloat16(v);
    lo = __float2bfloat16(v - __bfloat162float(hi));
}

__device__ __forceinline__ int win_row_to_token(int r) {
    int widx = r >> 6;
    int t    = r & 63;
    int b    = widx / (NWB * NWB);
    int wrem = widx - b * (NWB * NWB);
    int wh   = wrem / NWB;
    int ww   = wrem - wh * NWB;
    int ty   = t >> 3, tx = t & 7;
    int hp   = wh * WIN + ty + SHIFT; if (hp >= HH) hp -= HH;
    int wp   = ww * WIN + tx + SHIFT; if (wp >= WW) wp -= WW;
    return b * L + hp * WW + wp;
}

// ---------------- all-weights fp32 [K][N] -> split bf16 [2K][N], one launch ----------------
__global__ void cvt_all(const float* __restrict__ qkv_w, const float* __restrict__ proj_w,
                        const float* __restrict__ fc1_w, const float* __restrict__ fc2_w,
                        __nv_bfloat16* __restrict__ wq, __nv_bfloat16* __restrict__ wp,
                        __nv_bfloat16* __restrict__ w1, __nv_bfloat16* __restrict__ w2) {
    int i = blockIdx.x * blockDim.x + threadIdx.x;
    const float* src; __nv_bfloat16* dst; int KN;
    int j = i;
    if (j < 196608)                     { src = qkv_w;  dst = wq; KN = 196608; }
    else if ((j -= 196608) < 65536)     { src = proj_w; dst = wp; KN = 65536; }
    else if ((j -= 65536)  < 262144)    { src = fc1_w;  dst = w1; KN = 262144; }
    else if ((j -= 262144) < 262144)    { src = fc2_w;  dst = w2; KN = 262144; }
    else return;
    __nv_bfloat16 hi, lo;
    split2(src[j], hi, lo);
    dst[j]      = hi;
    dst[KN + j] = lo;
}

// ---------------- LayerNorm fp32 -> split bf16 [M][2K], one warp per row ----------------
__global__ void ln_split_kernel(const float* __restrict__ x, const float* __restrict__ g,
                                const float* __restrict__ b, __nv_bfloat16* __restrict__ out) {
    int gw   = (blockIdx.x * blockDim.x + threadIdx.x) >> 5;
    int lane = threadIdx.x & 31;
    const float4* rp = (const float4*)(x + (size_t)gw * DIM);
    float4 a0 = rp[lane * 2], a1 = rp[lane * 2 + 1];
    float s  = a0.x + a0.y + a0.z + a0.w + a1.x + a1.y + a1.z + a1.w;
    float sq = a0.x*a0.x + a0.y*a0.y + a0.z*a0.z + a0.w*a0.w
             + a1.x*a1.x + a1.y*a1.y + a1.z*a1.z + a1.w*a1.w;
    #pragma unroll
    for (int o = 16; o; o >>= 1) {
        s  += __shfl_xor_sync(0xffffffffu, s,  o);
        sq += __shfl_xor_sync(0xffffffffu, sq, o);
    }
    float mean = s * (1.0f / DIM);
    float var  = sq * (1.0f / DIM) - mean * mean;
    float rstd = rsqrtf(var + 1e-5f);
    const float4* gp = (const float4*)g;
    const float4* bp = (const float4*)b;
    float4 g0 = gp[lane*2], g1 = gp[lane*2+1], b0 = bp[lane*2], b1 = bp[lane*2+1];
    float y[8];
    y[0] = (a0.x - mean) * rstd * g0.x + b0.x;
    y[1] = (a0.y - mean) * rstd * g0.y + b0.y;
    y[2] = (a0.z - mean) * rstd * g0.z + b0.z;
    y[3] = (a0.w - mean) * rstd * g0.w + b0.w;
    y[4] = (a1.x - mean) * rstd * g1.x + b1.x;
    y[5] = (a1.y - mean) * rstd * g1.y + b1.y;
    y[6] = (a1.z - mean) * rstd * g1.z + b1.z;
    y[7] = (a1.w - mean) * rstd * g1.w + b1.w;
    __nv_bfloat16 hi[8], lo[8];
    #pragma unroll
    for (int i = 0; i < 8; i++) split2(y[i], hi[i], lo[i]);
    __nv_bfloat16* base = out + (size_t)gw * (2 * DIM) + lane * 8;
    *(uint4*)(base)       = *(uint4*)hi;
    *(uint4*)(base + DIM) = *(uint4*)lo;
}

// ---------------- GEMM: split products, bf16 wmma, 64x64 warp tiles, 3-stage pipeline ----------------
static constexpr int Bb_M = 128, Bb_N = 128, Bb_K = 32, STAGES = 3;
static constexpr int NTHREADS = 128;           // 4 warps, 2(M) x 2(N), warp tile 64x64
static constexpr int LDA = Bb_K + 8;     // 40
static constexpr int LDB = Bb_N + 8;     // 136
static constexpr int AH_ST = Bb_M * LDA; // 5120
static constexpr int BH_ST = Bb_K * LDB; // 4352
static constexpr int STAGE_E = 2 * AH_ST + 2 * BH_ST;   // 18944 elems (37888 B)
static constexpr int LDC_S = 132;
static constexpr int SMEM_GEMM = STAGES * STAGE_E * 2;  // 113664 B

static constexpr int EPI_QKV = 0, EPI_PROJ = 1, EPI_FC1 = 2, EPI_FC2 = 3;

__device__ __forceinline__ void cpa16(void* sptr, const void* gptr) {
    unsigned int s = (unsigned int)__cvta_generic_to_shared(sptr);
    asm volatile("cp.async.cg.shared.global [%0], [%1], 16;\n" :: "r"(s), "l"(gptr));
}

// TERMS = 3: Ahi*Bhi + Alo*Bhi + Ahi*Blo ; TERMS = 2: Ahi*Bhi + Alo*Bhi
template<int EPI, int TERMS>
__global__ void __launch_bounds__(NTHREADS, 2)
gemm2(const __nv_bfloat16* __restrict__ A,      // [M][2K]
      const __nv_bfloat16* __restrict__ Bm,     // [2K][N]
      const float* __restrict__ bias,
      const float* __restrict__ res,
      float* __restrict__ outF,
      __nv_bfloat16* __restrict__ out2,
      int N, int K) {
    extern __shared__ char smem[];
    __nv_bfloat16* sm = (__nv_bfloat16*)smem;
    float*         Cs = (float*)smem;

    int tid  = threadIdx.x;
    int warp = tid >> 5;
    int wm   = warp >> 1;          // 0..1  (64-row slab)
    int wn   = warp & 1;           // 0..1  (64-col slab)
    int bn   = blockIdx.x * Bb_N;  // N fastest: A-sharing CTAs co-resident
    int bm   = blockIdx.y * Bb_M;
    int K2   = 2 * K;
    int T    = K / Bb_K;

    wmma::fragment<wmma::accumulator, 16, 16, 16, float> acc[4][4];
    #pragma unroll
    for (int i = 0; i < 4; i++)
        #pragma unroll
        for (int j = 0; j < 4; j++)
            wmma::fill_fragment(acc[i][j], 0.0f);

    auto loads = [&](int t) {
        int k0 = t * Bb_K;
        int st = t % STAGES;
        __nv_bfloat16* AH = sm + st * STAGE_E;
        __nv_bfloat16* AL = AH + AH_ST;
        __nv_bfloat16* BH = AL + AH_ST;
        __nv_bfloat16* BL = BH + BH_ST;
        #pragma unroll
        for (int i = 0; i < 4; i++) {            // A: 512 chunks x 16B per comp
            int c = tid + i * NTHREADS;
            int r = c >> 2, cc = (c & 3) * 8;
            const __nv_bfloat16* src = A + (size_t)(bm + r) * K2 + k0 + cc;
            cpa16(&AH[r * LDA + cc], src);
            cpa16(&AL[r * LDA + cc], src + K);
        }
        #pragma unroll
        for (int i = 0; i < 4; i++) {            // B: 512 chunks x 16B per comp
            int c = tid + i * NTHREADS;
            int r = c >> 4, cc = (c & 15) * 8;
            cpa16(&BH[r * LDB + cc], Bm + (size_t)(k0 + r) * N + bn + cc);
            if (TERMS == 3)
                cpa16(&BL[r * LDB + cc], Bm + (size_t)(K + k0 + r) * N + bn + cc);
        }
        asm volatile("cp.async.commit_group;\n" ::);
    };

    loads(0);
    loads(1);

    for (int t = 0; t < T; t++) {
        asm volatile("cp.async.wait_group 1;\n" ::);   // stage t resident
        __syncthreads();                               // all warps done with stage t-1
        if (t + 2 < T) loads(t + 2);                   // overwrites stage (t-1)%3 — safe

        int st = t % STAGES;
        const __nv_bfloat16* AH = sm + st * STAGE_E;
        const __nv_bfloat16* AL = AH + AH_ST;
        const __nv_bfloat16* BH = AL + AH_ST;
        const __nv_bfloat16* BL = BH + BH_ST;

        #pragma unroll
        for (int kk = 0; kk < Bb_K; kk += 16) {
            wmma::fragment<wmma::matrix_a, 16, 16, 16, __nv_bfloat16, wmma::row_major> ah[4], al[4];
            wmma::fragment<wmma::matrix_b, 16, 16, 16, __nv_bfloat16, wmma::row_major> bf[4];
            #pragma unroll
            for (int i = 0; i < 4; i++) {
                wmma::load_matrix_sync(ah[i], &AH[(wm * 64 + i * 16) * LDA + kk], LDA);
                wmma::load_matrix_sync(al[i], &AL[(wm * 64 + i * 16) * LDA + kk], LDA);
            }
            #pragma unroll
            for (int j = 0; j < 4; j++)
                wmma::load_matrix_sync(bf[j], &BH[kk * LDB + wn * 64 + j * 16], LDB);
            #pragma unroll
            for (int i = 0; i < 4; i++)
                #pragma unroll
                for (int j = 0; j < 4; j++) {
                    wmma::mma_sync(acc[i][j], ah[i], bf[j], acc[i][j]);
                    wmma::mma_sync(acc[i][j], al[i], bf[j], acc[i][j]);
                }
            if (TERMS == 3) {
                #pragma unroll
                for (int j = 0; j < 4; j++)
                    wmma::load_matrix_sync(bf[j], &BL[kk * LDB + wn * 64 + j * 16], LDB);
                #pragma unroll
                for (int i = 0; i < 4; i++)
                    #pragma unroll
                    for (int j = 0; j < 4; j++)
                        wmma::mma_sync(acc[i][j], ah[i], bf[j], acc[i][j]);
            }
        }
    }

    asm volatile("cp.async.wait_all;\n" ::);
    __syncthreads();

    #pragma unroll
    for (int i = 0; i < 4; i++)
        #pragma unroll
        for (int j = 0; j < 4; j++)
            wmma::store_matrix_sync(&Cs[(wm * 64 + i * 16) * LDC_S + wn * 64 + j * 16],
                                    acc[i][j], LDC_S, wmma::mem_row_major);
    __syncthreads();

    // float4 epilogue: 4096 float4s / 128 threads = 32 each
    #pragma unroll 4
    for (int e = 0; e < 32; e++) {
        int idx = tid + e * NTHREADS;
        int r = idx >> 5;              // 0..127
        int c = (idx & 31) * 4;        // 0..124
        float4 v = *(float4*)&Cs[r * LDC_S + c];
        int gr = bm + r, gc = bn + c;
        float4 bv = *(const float4*)(bias + gc);
        if (EPI == EPI_QKV) {
            float4 o = {v.x + bv.x, v.y + bv.y, v.z + bv.z, v.w + bv.w};
            *(float4*)(outF + (size_t)gr * N + gc) = o;
        } else if (EPI == EPI_PROJ) {
            int tok = win_row_to_token(gr);
            size_t off = (size_t)tok * DIM + gc;
            float4 rv = *(const float4*)(res + off);
            float4 o = {v.x + bv.x + rv.x, v.y + bv.y + rv.y,
                        v.z + bv.z + rv.z, v.w + bv.w + rv.w};
            *(float4*)(outF + off) = o;
        } else if (EPI == EPI_FC1) {
            float tv[4] = {v.x + bv.x, v.y + bv.y, v.z + bv.z, v.w + bv.w};
            __nv_bfloat16 hi[4], lo[4];
            #pragma unroll
            for (int q = 0; q < 4; q++) {
                float gl = 0.5f * tv[q] * (1.0f + erff(tv[q] * 0.70710678118654752f));
                split2(gl, hi[q], lo[q]);
            }
            size_t base = (size_t)gr * (2 * HID) + gc;
            *(uint2*)(out2 + base)       = *(uint2*)hi;
            *(uint2*)(out2 + base + HID) = *(uint2*)lo;
        } else { // EPI_FC2
            size_t off = (size_t)gr * N + gc;
            float4 rv = *(const float4*)(res + off);
            float4 o = {v.x + bv.x + rv.x, v.y + bv.y + rv.y,
                        v.z + bv.z + rv.z, v.w + bv.w + rv.w};
            *(float4*)(outF + off) = o;
        }
    }
}

// ---------------- attention: one block per (window, head), 128 threads, tf32 ----------------
static constexpr int AQ_LD = 36;
static constexpr int AS_LD = 68;
static constexpr int OFF_Q = 0;
static constexpr int OFF_K = OFF_Q + 64 * AQ_LD;
static constexpr int OFF_V = OFF_K + 64 * AQ_LD;
static constexpr int OFF_S = OFF_V + 64 * AQ_LD;
static constexpr int OFF_P = OFF_S + 64 * AS_LD;
static constexpr int OFF_B = OFF_P + 64 * AS_LD;
static constexpr int OFF_T = OFF_B + 228;
static constexpr int ATT_SMEM = (OFF_T + 64) * 4;

template<class Frag>
__device__ __forceinline__ void to_tf32(Frag& f) {
    #pragma unroll
    for (int t = 0; t < f.num_elements; t++) f.x[t] = wmma::__float_to_tf32(f.x[t]);
}

__global__ void attn_kernel(const float* __restrict__ qkv,
                            const float* __restrict__ table,
                            __nv_bfloat16* __restrict__ out2) {
    extern __shared__ float sm[];
    float* sQ = sm + OFF_Q;
    float* sK = sm + OFF_K;
    float* sV = sm + OFF_V;
    float* sS = sm + OFF_S;
    float* sP = sm + OFF_P;
    float* sB = sm + OFF_B;
    int*   sTok = (int*)(sm + OFF_T);

    int widx = blockIdx.x, head = blockIdx.y;
    int tid = threadIdx.x, lane = tid & 31, w = tid >> 5;

    if (tid < 225) sB[tid] = table[tid * HEADS + head];
    if (tid < 64)  sTok[tid] = win_row_to_token(widx * 64 + tid);
    __syncthreads();

    #pragma unroll
    for (int i = 0; i < 4; i++) {
        int c = tid + i * 128;
        int r = c >> 3, cc = (c & 7) * 4;
        size_t base = (size_t)sTok[r] * (3 * DIM) + head * HD + cc;
        *(float4*)&sQ[r * AQ_LD + cc] = *(const float4*)&qkv[base];
        *(float4*)&sK[r * AQ_LD + cc] = *(const float4*)&qkv[base + DIM];
        *(float4*)&sV[r * AQ_LD + cc] = *(const float4*)&qkv[base + 2 * DIM];
    }
    __syncthreads();

    {
        wmma::fragment<wmma::accumulator, 16, 16, 8, float> acc[4];
        #pragma unroll
        for (int j = 0; j < 4; j++) wmma::fill_fragment(acc[j], 0.0f);
        #pragma unroll
        for (int kk = 0; kk < 32; kk += 8) {
            wmma::fragment<wmma::matrix_a, 16, 16, 8, wmma::precision::tf32, wmma::row_major> af;
            wmma::load_matrix_sync(af, &sQ[(w * 16) * AQ_LD + kk], AQ_LD);
            to_tf32(af);
            #pragma unroll
            for (int j = 0; j < 4; j++) {
                wmma::fragment<wmma::matrix_b, 16, 16, 8, wmma::precision::tf32, wmma::col_major> bf;
                wmma::load_matrix_sync(bf, &sK[(j * 16) * AQ_LD + kk], AQ_LD);
                to_tf32(bf);
                wmma::mma_sync(acc[j], af, bf, acc[j]);
            }
        }
        #pragma unroll
        for (int j = 0; j < 4; j++)
            wmma::store_matrix_sync(&sS[(w * 16) * AS_LD + j * 16], acc[j], AS_LD, wmma::mem_row_major);
    }
    __syncthreads();

    #pragma unroll 2
    for (int rr = 0; rr < 16; rr++) {
        int r = w * 16 + rr;
        int yi = r >> 3, xi = r & 7;
        int c0 = lane, c1 = lane + 32;
        int i0 = (yi - (c0 >> 3) + 7) * 15 + (xi - (c0 & 7) + 7);
        int i1 = (yi - (c1 >> 3) + 7) * 15 + (xi - (c1 & 7) + 7);
        float v0 = sS[r * AS_LD + c0] * SCALE + sB[i0];
        float v1 = sS[r * AS_LD + c1] * SCALE + sB[i1];
        float m = fmaxf(v0, v1);
        #pragma unroll
        for (int o = 16; o; o >>= 1) m = fmaxf(m, __shfl_xor_sync(0xffffffffu, m, o));
        float e0 = __expf(v0 - m), e1 = __expf(v1 - m);
        float s = e0 + e1;
        #pragma unroll
        for (int o = 16; o; o >>= 1) s += __shfl_xor_sync(0xffffffffu, s, o);
        float inv = 1.0f / s;
        sP[r * AS_LD + c0] = e0 * inv;
        sP[r * AS_LD + c1] = e1 * inv;
    }
    __syncthreads();

    {
        wmma::fragment<wmma::accumulator, 16, 16, 8, float> acc[2];
        #pragma unroll
        for (int j = 0; j < 2; j++) wmma::fill_fragment(acc[j], 0.0f);
        #pragma unroll
        for (int k0 = 0; k0 < 64; k0 += 8) {
            wmma::fragment<wmma::matrix_a, 16, 16, 8, wmma::precision::tf32, wmma::row_major> af;
            wmma::load_matrix_sync(af, &sP[(w * 16) * AS_LD + k0], AS_LD);
            to_tf32(af);
            #pragma unroll
            for (int j = 0; j < 2; j++) {
                wmma::fragment<wmma::matrix_b, 16, 16, 8, wmma::precision::tf32, wmma::row_major> bf;
                wmma::load_matrix_sync(bf, &sV[k0 * AQ_LD + j * 16], AQ_LD);
                to_tf32(bf);
                wmma::mma_sync(acc[j], af, bf, acc[j]);
            }
        }
        __syncthreads();
        #pragma unroll
        for (int j = 0; j < 2; j++)
            wmma::store_matrix_sync(&sS[(w * 16) * AS_LD + j * 16], acc[j], AS_LD, wmma::mem_row_major);
    }
    __syncthreads();

    #pragma unroll
    for (int i = 0; i < 16; i++) {
        int idx = tid + i * 128;
        int r = idx >> 5, c = idx & 31;
        float v = sS[r * AS_LD + c];
        __nv_bfloat16 hi, lo;
        split2(v, hi, lo);
        size_t base = ((size_t)widx * 64 + r) * (2 * DIM) + head * HD + c;
        out2[base]       = hi;
        out2[base + DIM] = lo;
    }
}

// ---------------- launch ----------------
extern "C" void kernel_launch(void* const* d_in, const int* in_sizes, int n_in,
                              void* d_out, int out_size) {
    const float* x        = (const float*)d_in[0];
    const float* norm1_g  = (const float*)d_in[1];
    const float* norm1_b  = (const float*)d_in[2];
    const float* qkv_w    = (const float*)d_in[3];
    const float* qkv_b    = (const float*)d_in[4];
    const float* bias_tab = (const float*)d_in[5];
    const float* proj_w   = (const float*)d_in[6];
    const float* proj_b   = (const float*)d_in[7];
    const float* norm2_g  = (const float*)d_in[8];
    const float* norm2_b  = (const float*)d_in[9];
    const float* fc1_w    = (const float*)d_in[10];
    const float* fc1_b    = (const float*)d_in[11];
    const float* fc2_w    = (const float*)d_in[12];
    const float* fc2_b    = (const float*)d_in[13];
    float* out            = (float*)d_out;

    void *p;
    cudaGetSymbolAddress(&p, g_h2);    __nv_bfloat16* ph2   = (__nv_bfloat16*)p;
    cudaGetSymbolAddress(&p, g_qkv);   float*         pqkv  = (float*)p;
    cudaGetSymbolAddress(&p, g_attn2); __nv_bfloat16* pat2  = (__nv_bfloat16*)p;
    cudaGetSymbolAddress(&p, g_x2);    float*         px2   = (float*)p;
    cudaGetSymbolAddress(&p, g_ln22);  __nv_bfloat16* pln22 = (__nv_bfloat16*)p;
    cudaGetSymbolAddress(&p, g_hid2);  __nv_bfloat16* phid2 = (__nv_bfloat16*)p;
    cudaGetSymbolAddress(&p, g_wqkv2); __nv_bfloat16* pwq2  = (__nv_bfloat16*)p;
    cudaGetSymbolAddress(&p, g_wproj2);__nv_bfloat16* pwp2  = (__nv_bfloat16*)p;
    cudaGetSymbolAddress(&p, g_wfc12); __nv_bfloat16* pw12  = (__nv_bfloat16*)p;
    cudaGetSymbolAddress(&p, g_wfc22); __nv_bfloat16* pw22  = (__nv_bfloat16*)p;

    cudaFuncSetAttribute((const void*)gemm2<EPI_QKV, 3>,  cudaFuncAttributeMaxDynamicSharedMemorySize, SMEM_GEMM);
    cudaFuncSetAttribute((const void*)gemm2<EPI_PROJ, 2>, cudaFuncAttributeMaxDynamicSharedMemorySize, SMEM_GEMM);
    cudaFuncSetAttribute((const void*)gemm2<EPI_FC1, 3>,  cudaFuncAttributeMaxDynamicSharedMemorySize, SMEM_GEMM);
    cudaFuncSetAttribute((const void*)gemm2<EPI_FC2, 2>,  cudaFuncAttributeMaxDynamicSharedMemorySize, SMEM_GEMM);
    cudaFuncSetAttribute(attn_kernel, cudaFuncAttributeMaxDynamicSharedMemorySize, ATT_SMEM);

    const int MT = MROWS / Bb_M;   // 1152

    // 0. split weights (one launch)
    cvt_all<<<(786432 + 255)/256, 256>>>(qkv_w, proj_w, fc1_w, fc2_w, pwq2, pwp2, pw12, pw22);

    // 1. LN1 -> h2
    ln_split_kernel<<<MROWS/8, 256>>>(x, norm1_g, norm1_b, ph2);

    // 2. QKV GEMM (K=256, N=768, 3-term)
    gemm2<EPI_QKV, 3><<<dim3(3*DIM/Bb_N, MT), NTHREADS, SMEM_GEMM>>>(
        ph2, pwq2, qkv_b, nullptr, pqkv, nullptr, 3*DIM, DIM);

    // 3. windowed attention (tf32) -> attn2 (windowed order)
    attn_kernel<<<dim3(NWIN, HEADS), 128, ATT_SMEM>>>(pqkv, bias_tab, pat2);

    // 4. proj GEMM (K=256, N=256, 2-term) + shortcut scatter -> x2
    gemm2<EPI_PROJ, 2><<<dim3(DIM/Bb_N, MT), NTHREADS, SMEM_GEMM>>>(
        pat2, pwp2, proj_b, x, px2, nullptr, DIM, DIM);

    // 5. LN2 -> ln22
    ln_split_kernel<<<MROWS/8, 256>>>(px2, norm2_g, norm2_b, pln22);

    // 6. fc1 GEMM (K=256, N=1024, 3-term) + GELU -> hid2
    gemm2<EPI_FC1, 3><<<dim3(HID/Bb_N, MT), NTHREADS, SMEM_GEMM>>>(
        pln22, pw12, fc1_b, nullptr, nullptr, phid2, HID, DIM);

    // 7. fc2 GEMM (K=1024, N=256, 2-term) + residual -> out
    gemm2<EPI_FC2, 2><<<dim3(DIM/Bb_N, MT), NTHREADS, SMEM_GEMM>>>(
        phid2, pw22, fc2_b, px2, out, nullptr, DIM, HID);
}

// round 9
// speedup vs baseline: 2.4281x; 1.2066x over previous
#include <cuda_runtime.h>
#include <cuda_bf16.h>
#include <mma.h>
#include <math.h>
#include <cstdint>

using namespace nvcuda;

// ---------------- problem constants ----------------
static constexpr int BB    = 4;
static constexpr int HH    = 192;
static constexpr int WW    = 192;
static constexpr int DIM   = 256;
static constexpr int HEADS = 8;
static constexpr int HD    = 32;
static constexpr int WIN   = 8;
static constexpr int SHIFT = 4;
static constexpr int HID   = 1024;

static constexpr int L     = HH * WW;          // 36864
static constexpr int MROWS = BB * L;           // 147456
static constexpr int NWB   = HH / WIN;         // 24
static constexpr int NWIN  = BB * NWB * NWB;   // 2304
static constexpr float SCALE = 0.17677669529663687f; // 1/sqrt(32)

// ---------------- scratch ----------------
// 2-component storage: A2[M][2K] = [hi | lo], W2[2K][N] = [hi ; lo].
__device__ __nv_bfloat16 g_h2   [(size_t)MROWS * 2 * DIM];
__device__ float         g_qkv  [(size_t)MROWS * 3 * DIM];
__device__ __nv_bfloat16 g_attn2[(size_t)MROWS * 2 * DIM];
__device__ float         g_x2   [(size_t)MROWS * DIM];
__device__ __nv_bfloat16 g_ln22 [(size_t)MROWS * 2 * DIM];
__device__ __nv_bfloat16 g_hid2 [(size_t)MROWS * 2 * HID];

__device__ __nv_bfloat16 g_wqkv2 [2 * DIM * 3 * DIM];
__device__ __nv_bfloat16 g_wproj2[2 * DIM * DIM];
__device__ __nv_bfloat16 g_wfc12 [2 * DIM * HID];
__device__ __nv_bfloat16 g_wfc22 [2 * HID * DIM];

__device__ __forceinline__ void split2(float v, __nv_bfloat16& hi, __nv_bfloat16& lo) {
    hi = __float2bfloat16(v);
    lo = __float2bfloat16(v - __bfloat162float(hi));
}

__device__ __forceinline__ int win_row_to_token(int r) {
    int widx = r >> 6;
    int t    = r & 63;
    int b    = widx / (NWB * NWB);
    int wrem = widx - b * (NWB * NWB);
    int wh   = wrem / NWB;
    int ww   = wrem - wh * NWB;
    int ty   = t >> 3, tx = t & 7;
    int hp   = wh * WIN + ty + SHIFT; if (hp >= HH) hp -= HH;
    int wp   = ww * WIN + tx + SHIFT; if (wp >= WW) wp -= WW;
    return b * L + hp * WW + wp;
}

// ---------------- all-weights fp32 [K][N] -> split bf16 [2K][N], one launch ----------------
__global__ void cvt_all(const float* __restrict__ qkv_w, const float* __restrict__ proj_w,
                        const float* __restrict__ fc1_w, const float* __restrict__ fc2_w,
                        __nv_bfloat16* __restrict__ wq, __nv_bfloat16* __restrict__ wp,
                        __nv_bfloat16* __restrict__ w1, __nv_bfloat16* __restrict__ w2) {
    int i = blockIdx.x * blockDim.x + threadIdx.x;
    const float* src; __nv_bfloat16* dst; int KN;
    int j = i;
    if (j < 196608)                     { src = qkv_w;  dst = wq; KN = 196608; }
    else if ((j -= 196608) < 65536)     { src = proj_w; dst = wp; KN = 65536; }
    else if ((j -= 65536)  < 262144)    { src = fc1_w;  dst = w1; KN = 262144; }
    else if ((j -= 262144) < 262144)    { src = fc2_w;  dst = w2; KN = 262144; }
    else return;
    __nv_bfloat16 hi, lo;
    split2(src[j], hi, lo);
    dst[j]      = hi;
    dst[KN + j] = lo;
}

// ---------------- LayerNorm fp32 -> split bf16 [M][2K], one warp per row ----------------
__global__ void ln_split_kernel(const float* __restrict__ x, const float* __restrict__ g,
                                const float* __restrict__ b, __nv_bfloat16* __restrict__ out) {
    int gw   = (blockIdx.x * blockDim.x + threadIdx.x) >> 5;
    int lane = threadIdx.x & 31;
    const float4* rp = (const float4*)(x + (size_t)gw * DIM);
    float4 a0 = rp[lane * 2], a1 = rp[lane * 2 + 1];
    float s  = a0.x + a0.y + a0.z + a0.w + a1.x + a1.y + a1.z + a1.w;
    float sq = a0.x*a0.x + a0.y*a0.y + a0.z*a0.z + a0.w*a0.w
             + a1.x*a1.x + a1.y*a1.y + a1.z*a1.z + a1.w*a1.w;
    #pragma unroll
    for (int o = 16; o; o >>= 1) {
        s  += __shfl_xor_sync(0xffffffffu, s,  o);
        sq += __shfl_xor_sync(0xffffffffu, sq, o);
    }
    float mean = s * (1.0f / DIM);
    float var  = sq * (1.0f / DIM) - mean * mean;
    float rstd = rsqrtf(var + 1e-5f);
    const float4* gp = (const float4*)g;
    const float4* bp = (const float4*)b;
    float4 g0 = gp[lane*2], g1 = gp[lane*2+1], b0 = bp[lane*2], b1 = bp[lane*2+1];
    float y[8];
    y[0] = (a0.x - mean) * rstd * g0.x + b0.x;
    y[1] = (a0.y - mean) * rstd * g0.y + b0.y;
    y[2] = (a0.z - mean) * rstd * g0.z + b0.z;
    y[3] = (a0.w - mean) * rstd * g0.w + b0.w;
    y[4] = (a1.x - mean) * rstd * g1.x + b1.x;
    y[5] = (a1.y - mean) * rstd * g1.y + b1.y;
    y[6] = (a1.z - mean) * rstd * g1.z + b1.z;
    y[7] = (a1.w - mean) * rstd * g1.w + b1.w;
    __nv_bfloat16 hi[8], lo[8];
    #pragma unroll
    for (int i = 0; i < 8; i++) split2(y[i], hi[i], lo[i]);
    __nv_bfloat16* base = out + (size_t)gw * (2 * DIM) + lane * 8;
    *(uint4*)(base)       = *(uint4*)hi;
    *(uint4*)(base + DIM) = *(uint4*)lo;
}

// ---------------- GEMM: split products, bf16 wmma, 64x64 warp tiles, 3-stage pipeline ----------------
static constexpr int Bb_M = 128, Bb_N = 128, Bb_K = 32, STAGES = 3;
static constexpr int NTHREADS = 128;           // 4 warps, 2(M) x 2(N), warp tile 64x64
static constexpr int LDA = Bb_K + 8;     // 40
static constexpr int LDB = Bb_N + 8;     // 136
static constexpr int AH_ST = Bb_M * LDA; // 5120
static constexpr int BH_ST = Bb_K * LDB; // 4352
static constexpr int STAGE_E = 2 * AH_ST + 2 * BH_ST;   // 18944 elems (37888 B)
static constexpr int LDC_S = 132;
static constexpr int SMEM_GEMM = STAGES * STAGE_E * 2;  // 113664 B

static constexpr int EPI_QKV = 0, EPI_PROJ = 1, EPI_FC1 = 2, EPI_FC2 = 3;

__device__ __forceinline__ void cpa16(void* sptr, const void* gptr) {
    unsigned int s = (unsigned int)__cvta_generic_to_shared(sptr);
    asm volatile("cp.async.cg.shared.global [%0], [%1], 16;\n" :: "r"(s), "l"(gptr));
}

// TERMS = 2: Ahi*Bhi + Alo*Bhi  (weight-lo dropped everywhere; error diluted by residuals)
template<int EPI, int TERMS>
__global__ void __launch_bounds__(NTHREADS, 2)
gemm2(const __nv_bfloat16* __restrict__ A,      // [M][2K]
      const __nv_bfloat16* __restrict__ Bm,     // [2K][N]
      const float* __restrict__ bias,
      const float* __restrict__ res,
      float* __restrict__ outF,
      __nv_bfloat16* __restrict__ out2,
      int N, int K) {
    extern __shared__ char smem[];
    __nv_bfloat16* sm = (__nv_bfloat16*)smem;
    float*         Cs = (float*)smem;

    int tid  = threadIdx.x;
    int warp = tid >> 5;
    int wm   = warp >> 1;          // 0..1  (64-row slab)
    int wn   = warp & 1;           // 0..1  (64-col slab)
    int bn   = blockIdx.x * Bb_N;
    int bm   = blockIdx.y * Bb_M;
    int K2   = 2 * K;
    int T    = K / Bb_K;

    wmma::fragment<wmma::accumulator, 16, 16, 16, float> acc[4][4];
    #pragma unroll
    for (int i = 0; i < 4; i++)
        #pragma unroll
        for (int j = 0; j < 4; j++)
            wmma::fill_fragment(acc[i][j], 0.0f);

    auto loads = [&](int t) {
        int k0 = t * Bb_K;
        int st = t % STAGES;
        __nv_bfloat16* AH = sm + st * STAGE_E;
        __nv_bfloat16* AL = AH + AH_ST;
        __nv_bfloat16* BH = AL + AH_ST;
        __nv_bfloat16* BL = BH + BH_ST;
        #pragma unroll
        for (int i = 0; i < 4; i++) {
            int c = tid + i * NTHREADS;
            int r = c >> 2, cc = (c & 3) * 8;
            const __nv_bfloat16* src = A + (size_t)(bm + r) * K2 + k0 + cc;
            cpa16(&AH[r * LDA + cc], src);
            cpa16(&AL[r * LDA + cc], src + K);
        }
        #pragma unroll
        for (int i = 0; i < 4; i++) {
            int c = tid + i * NTHREADS;
            int r = c >> 4, cc = (c & 15) * 8;
            cpa16(&BH[r * LDB + cc], Bm + (size_t)(k0 + r) * N + bn + cc);
            if (TERMS == 3)
                cpa16(&BL[r * LDB + cc], Bm + (size_t)(K + k0 + r) * N + bn + cc);
        }
        asm volatile("cp.async.commit_group;\n" ::);
    };

    loads(0);
    loads(1);

    for (int t = 0; t < T; t++) {
        asm volatile("cp.async.wait_group 1;\n" ::);
        __syncthreads();
        if (t + 2 < T) loads(t + 2);

        int st = t % STAGES;
        const __nv_bfloat16* AH = sm + st * STAGE_E;
        const __nv_bfloat16* AL = AH + AH_ST;
        const __nv_bfloat16* BH = AL + AH_ST;
        const __nv_bfloat16* BL = BH + BH_ST;

        #pragma unroll
        for (int kk = 0; kk < Bb_K; kk += 16) {
            wmma::fragment<wmma::matrix_a, 16, 16, 16, __nv_bfloat16, wmma::row_major> ah[4], al[4];
            wmma::fragment<wmma::matrix_b, 16, 16, 16, __nv_bfloat16, wmma::row_major> bf[4];
            #pragma unroll
            for (int i = 0; i < 4; i++) {
                wmma::load_matrix_sync(ah[i], &AH[(wm * 64 + i * 16) * LDA + kk], LDA);
                wmma::load_matrix_sync(al[i], &AL[(wm * 64 + i * 16) * LDA + kk], LDA);
            }
            #pragma unroll
            for (int j = 0; j < 4; j++)
                wmma::load_matrix_sync(bf[j], &BH[kk * LDB + wn * 64 + j * 16], LDB);
            #pragma unroll
            for (int i = 0; i < 4; i++)
                #pragma unroll
                for (int j = 0; j < 4; j++) {
                    wmma::mma_sync(acc[i][j], ah[i], bf[j], acc[i][j]);
                    wmma::mma_sync(acc[i][j], al[i], bf[j], acc[i][j]);
                }
            if (TERMS == 3) {
                #pragma unroll
                for (int j = 0; j < 4; j++)
                    wmma::load_matrix_sync(bf[j], &BL[kk * LDB + wn * 64 + j * 16], LDB);
                #pragma unroll
                for (int i = 0; i < 4; i++)
                    #pragma unroll
                    for (int j = 0; j < 4; j++)
                        wmma::mma_sync(acc[i][j], ah[i], bf[j], acc[i][j]);
            }
        }
    }

    asm volatile("cp.async.wait_all;\n" ::);
    __syncthreads();

    #pragma unroll
    for (int i = 0; i < 4; i++)
        #pragma unroll
        for (int j = 0; j < 4; j++)
            wmma::store_matrix_sync(&Cs[(wm * 64 + i * 16) * LDC_S + wn * 64 + j * 16],
                                    acc[i][j], LDC_S, wmma::mem_row_major);
    __syncthreads();

    #pragma unroll 4
    for (int e = 0; e < 32; e++) {
        int idx = tid + e * NTHREADS;
        int r = idx >> 5;
        int c = (idx & 31) * 4;
        float4 v = *(float4*)&Cs[r * LDC_S + c];
        int gr = bm + r, gc = bn + c;
        float4 bv = *(const float4*)(bias + gc);
        if (EPI == EPI_QKV) {
            float4 o = {v.x + bv.x, v.y + bv.y, v.z + bv.z, v.w + bv.w};
            *(float4*)(outF + (size_t)gr * N + gc) = o;
        } else if (EPI == EPI_PROJ) {
            int tok = win_row_to_token(gr);
            size_t off = (size_t)tok * DIM + gc;
            float4 rv = *(const float4*)(res + off);
            float4 o = {v.x + bv.x + rv.x, v.y + bv.y + rv.y,
                        v.z + bv.z + rv.z, v.w + bv.w + rv.w};
            *(float4*)(outF + off) = o;
        } else if (EPI == EPI_FC1) {
            float tv[4] = {v.x + bv.x, v.y + bv.y, v.z + bv.z, v.w + bv.w};
            __nv_bfloat16 hi[4], lo[4];
            #pragma unroll
            for (int q = 0; q < 4; q++) {
                float gl = 0.5f * tv[q] * (1.0f + erff(tv[q] * 0.70710678118654752f));
                split2(gl, hi[q], lo[q]);
            }
            size_t base = (size_t)gr * (2 * HID) + gc;
            *(uint2*)(out2 + base)       = *(uint2*)hi;
            *(uint2*)(out2 + base + HID) = *(uint2*)lo;
        } else { // EPI_FC2
            size_t off = (size_t)gr * N + gc;
            float4 rv = *(const float4*)(res + off);
            float4 o = {v.x + bv.x + rv.x, v.y + bv.y + rv.y,
                        v.z + bv.z + rv.z, v.w + bv.w + rv.w};
            *(float4*)(outF + off) = o;
        }
    }
}

// ---------------- attention: one block per (window, head), 128 threads, tf32 ----------------
// sP eliminated: softmax in-place in sS; PV is warp-local (each warp reads/writes only
// its own 16 rows of sS) -> 46.2 KB smem -> 4 CTAs/SM instead of 3.
static constexpr int AQ_LD = 36;
static constexpr int AS_LD = 68;
static constexpr int OFF_Q = 0;
static constexpr int OFF_K = OFF_Q + 64 * AQ_LD;     // 2304
static constexpr int OFF_V = OFF_K + 64 * AQ_LD;     // 4608
static constexpr int OFF_S = OFF_V + 64 * AQ_LD;     // 6912
static constexpr int OFF_B = OFF_S + 64 * AS_LD;     // 11264
static constexpr int OFF_T = OFF_B + 228;            // 11492
static constexpr int ATT_SMEM = (OFF_T + 64) * 4;    // 46224 B

template<class Frag>
__device__ __forceinline__ void to_tf32(Frag& f) {
    #pragma unroll
    for (int t = 0; t < f.num_elements; t++) f.x[t] = wmma::__float_to_tf32(f.x[t]);
}

__global__ void attn_kernel(const float* __restrict__ qkv,
                            const float* __restrict__ table,
                            __nv_bfloat16* __restrict__ out2) {
    extern __shared__ float sm[];
    float* sQ = sm + OFF_Q;
    float* sK = sm + OFF_K;
    float* sV = sm + OFF_V;
    float* sS = sm + OFF_S;
    float* sB = sm + OFF_B;
    int*   sTok = (int*)(sm + OFF_T);

    int widx = blockIdx.x, head = blockIdx.y;
    int tid = threadIdx.x, lane = tid & 31, w = tid >> 5;

    if (tid < 225) sB[tid] = table[tid * HEADS + head];
    if (tid < 64)  sTok[tid] = win_row_to_token(widx * 64 + tid);
    __syncthreads();

    #pragma unroll
    for (int i = 0; i < 4; i++) {
        int c = tid + i * 128;
        int r = c >> 3, cc = (c & 7) * 4;
        size_t base = (size_t)sTok[r] * (3 * DIM) + head * HD + cc;
        *(float4*)&sQ[r * AQ_LD + cc] = *(const float4*)&qkv[base];
        *(float4*)&sK[r * AQ_LD + cc] = *(const float4*)&qkv[base + DIM];
        *(float4*)&sV[r * AQ_LD + cc] = *(const float4*)&qkv[base + 2 * DIM];
    }
    __syncthreads();

    // S = Q @ K^T  (warp w -> rows [w*16, w*16+16))
    {
        wmma::fragment<wmma::accumulator, 16, 16, 8, float> acc[4];
        #pragma unroll
        for (int j = 0; j < 4; j++) wmma::fill_fragment(acc[j], 0.0f);
        #pragma unroll
        for (int kk = 0; kk < 32; kk += 8) {
            wmma::fragment<wmma::matrix_a, 16, 16, 8, wmma::precision::tf32, wmma::row_major> af;
            wmma::load_matrix_sync(af, &sQ[(w * 16) * AQ_LD + kk], AQ_LD);
            to_tf32(af);
            #pragma unroll
            for (int j = 0; j < 4; j++) {
                wmma::fragment<wmma::matrix_b, 16, 16, 8, wmma::precision::tf32, wmma::col_major> bf;
                wmma::load_matrix_sync(bf, &sK[(j * 16) * AQ_LD + kk], AQ_LD);
                to_tf32(bf);
                wmma::mma_sync(acc[j], af, bf, acc[j]);
            }
        }
        #pragma unroll
        for (int j = 0; j < 4; j++)
            wmma::store_matrix_sync(&sS[(w * 16) * AS_LD + j * 16], acc[j], AS_LD, wmma::mem_row_major);
    }
    // no block sync needed: softmax below touches only this warp's rows

    // softmax(S*scale + relbias) in place (warp-local rows)
    #pragma unroll 2
    for (int rr = 0; rr < 16; rr++) {
        int r = w * 16 + rr;
        int yi = r >> 3, xi = r & 7;
        int c0 = lane, c1 = lane + 32;
        int i0 = (yi - (c0 >> 3) + 7) * 15 + (xi - (c0 & 7) + 7);
        int i1 = (yi - (c1 >> 3) + 7) * 15 + (xi - (c1 & 7) + 7);
        float v0 = sS[r * AS_LD + c0] * SCALE + sB[i0];
        float v1 = sS[r * AS_LD + c1] * SCALE + sB[i1];
        float m = fmaxf(v0, v1);
        #pragma unroll
        for (int o = 16; o; o >>= 1) m = fmaxf(m, __shfl_xor_sync(0xffffffffu, m, o));
        float e0 = __expf(v0 - m), e1 = __expf(v1 - m);
        float s = e0 + e1;
        #pragma unroll
        for (int o = 16; o; o >>= 1) s += __shfl_xor_sync(0xffffffffu, s, o);
        float inv = 1.0f / s;
        sS[r * AS_LD + c0] = e0 * inv;
        sS[r * AS_LD + c1] = e1 * inv;
    }
    __syncwarp();

    // O = P @ V  (A-fragments from own rows of sS; store O back to own rows)
    {
        wmma::fragment<wmma::accumulator, 16, 16, 8, float> acc[2];
        #pragma unroll
        for (int j = 0; j < 2; j++) wmma::fill_fragment(acc[j], 0.0f);
        #pragma unroll
        for (int k0 = 0; k0 < 64; k0 += 8) {
            wmma::fragment<wmma::matrix_a, 16, 16, 8, wmma::precision::tf32, wmma::row_major> af;
            wmma::load_matrix_sync(af, &sS[(w * 16) * AS_LD + k0], AS_LD);
            to_tf32(af);
            #pragma unroll
            for (int j = 0; j < 2; j++) {
                wmma::fragment<wmma::matrix_b, 16, 16, 8, wmma::precision::tf32, wmma::row_major> bf;
                wmma::load_matrix_sync(bf, &sV[k0 * AQ_LD + j * 16], AQ_LD);
                to_tf32(bf);
                wmma::mma_sync(acc[j], af, bf, acc[j]);
            }
        }
        #pragma unroll
        for (int j = 0; j < 2; j++)
            wmma::store_matrix_sync(&sS[(w * 16) * AS_LD + j * 16], acc[j], AS_LD, wmma::mem_row_major);
    }
    __syncthreads();   // output loop below reads rows across warps

    // write O (windowed row order) as hi|lo split for proj GEMM
    #pragma unroll
    for (int i = 0; i < 16; i++) {
        int idx = tid + i * 128;
        int r = idx >> 5, c = idx & 31;
        float v = sS[r * AS_LD + c];
        __nv_bfloat16 hi, lo;
        split2(v, hi, lo);
        size_t base = ((size_t)widx * 64 + r) * (2 * DIM) + head * HD + c;
        out2[base]       = hi;
        out2[base + DIM] = lo;
    }
}

// ---------------- launch ----------------
extern "C" void kernel_launch(void* const* d_in, const int* in_sizes, int n_in,
                              void* d_out, int out_size) {
    const float* x        = (const float*)d_in[0];
    const float* norm1_g  = (const float*)d_in[1];
    const float* norm1_b  = (const float*)d_in[2];
    const float* qkv_w    = (const float*)d_in[3];
    const float* qkv_b    = (const float*)d_in[4];
    const float* bias_tab = (const float*)d_in[5];
    const float* proj_w   = (const float*)d_in[6];
    const float* proj_b   = (const float*)d_in[7];
    const float* norm2_g  = (const float*)d_in[8];
    const float* norm2_b  = (const float*)d_in[9];
    const float* fc1_w    = (const float*)d_in[10];
    const float* fc1_b    = (const float*)d_in[11];
    const float* fc2_w    = (const float*)d_in[12];
    const float* fc2_b    = (const float*)d_in[13];
    float* out            = (float*)d_out;

    void *p;
    cudaGetSymbolAddress(&p, g_h2);    __nv_bfloat16* ph2   = (__nv_bfloat16*)p;
    cudaGetSymbolAddress(&p, g_qkv);   float*         pqkv  = (float*)p;
    cudaGetSymbolAddress(&p, g_attn2); __nv_bfloat16* pat2  = (__nv_bfloat16*)p;
    cudaGetSymbolAddress(&p, g_x2);    float*         px2   = (float*)p;
    cudaGetSymbolAddress(&p, g_ln22);  __nv_bfloat16* pln22 = (__nv_bfloat16*)p;
    cudaGetSymbolAddress(&p, g_hid2);  __nv_bfloat16* phid2 = (__nv_bfloat16*)p;
    cudaGetSymbolAddress(&p, g_wqkv2); __nv_bfloat16* pwq2  = (__nv_bfloat16*)p;
    cudaGetSymbolAddress(&p, g_wproj2);__nv_bfloat16* pwp2  = (__nv_bfloat16*)p;
    cudaGetSymbolAddress(&p, g_wfc12); __nv_bfloat16* pw12  = (__nv_bfloat16*)p;
    cudaGetSymbolAddress(&p, g_wfc22); __nv_bfloat16* pw22  = (__nv_bfloat16*)p;

    cudaFuncSetAttribute((const void*)gemm2<EPI_QKV, 2>,  cudaFuncAttributeMaxDynamicSharedMemorySize, SMEM_GEMM);
    cudaFuncSetAttribute((const void*)gemm2<EPI_PROJ, 2>, cudaFuncAttributeMaxDynamicSharedMemorySize, SMEM_GEMM);
    cudaFuncSetAttribute((const void*)gemm2<EPI_FC1, 2>,  cudaFuncAttributeMaxDynamicSharedMemorySize, SMEM_GEMM);
    cudaFuncSetAttribute((const void*)gemm2<EPI_FC2, 2>,  cudaFuncAttributeMaxDynamicSharedMemorySize, SMEM_GEMM);
    cudaFuncSetAttribute(attn_kernel, cudaFuncAttributeMaxDynamicSharedMemorySize, ATT_SMEM);

    const int MT = MROWS / Bb_M;   // 1152

    // 0. split weights (one launch)
    cvt_all<<<(786432 + 255)/256, 256>>>(qkv_w, proj_w, fc1_w, fc2_w, pwq2, pwp2, pw12, pw22);

    // 1. LN1 -> h2
    ln_split_kernel<<<MROWS/8, 256>>>(x, norm1_g, norm1_b, ph2);

    // 2. QKV GEMM (K=256, N=768, 2-term)
    gemm2<EPI_QKV, 2><<<dim3(3*DIM/Bb_N, MT), NTHREADS, SMEM_GEMM>>>(
        ph2, pwq2, qkv_b, nullptr, pqkv, nullptr, 3*DIM, DIM);

    // 3. windowed attention (tf32) -> attn2 (windowed order)
    attn_kernel<<<dim3(NWIN, HEADS), 128, ATT_SMEM>>>(pqkv, bias_tab, pat2);

    // 4. proj GEMM (K=256, N=256, 2-term) + shortcut scatter -> x2
    gemm2<EPI_PROJ, 2><<<dim3(DIM/Bb_N, MT), NTHREADS, SMEM_GEMM>>>(
        pat2, pwp2, proj_b, x, px2, nullptr, DIM, DIM);

    // 5. LN2 -> ln22
    ln_split_kernel<<<MROWS/8, 256>>>(px2, norm2_g, norm2_b, pln22);

    // 6. fc1 GEMM (K=256, N=1024, 2-term) + GELU -> hid2
    gemm2<EPI_FC1, 2><<<dim3(HID/Bb_N, MT), NTHREADS, SMEM_GEMM>>>(
        pln22, pw12, fc1_b, nullptr, nullptr, phid2, HID, DIM);

    // 7. fc2 GEMM (K=1024, N=256, 2-term) + residual -> out
    gemm2<EPI_FC2, 2><<<dim3(DIM/Bb_N, MT), NTHREADS, SMEM_GEMM>>>(
        phid2, pw22, fc2_b, px2, out, nullptr, DIM, HID);
}